// round 12
// baseline (speedup 1.0000x reference)
#include <cuda_runtime.h>
#include <cuda_bf16.h>
#include <math.h>
#include <stdint.h>

// Problem constants
constexpr int B_   = 2;
constexpr int S_   = 2048;
constexpr int H_   = 4096;
constexpr int NH_  = 32;
constexpr int NKV_ = 8;
constexpr int HD_  = 128;
constexpr int BS_  = B_ * S_;        // 4096 rows
constexpr int QD_  = NH_ * HD_;      // 4096
constexpr int KD_  = NKV_ * HD_;     // 1024
constexpr int QKVD_ = QD_ + 2 * KD_; // 6144

// ---------------------------------------------------------------------------
// Scratch (device globals; no allocation allowed)
// ---------------------------------------------------------------------------
__device__ float g_qkv[(size_t)BS_ * QKVD_];   // fused QKV GEMM out (fp32)

// split-bf16 operands (GEMM)
__device__ __nv_bfloat16 g_hs_hi[(size_t)BS_ * H_];
__device__ __nv_bfloat16 g_hs_lo[(size_t)BS_ * H_];
__device__ __nv_bfloat16 g_at_hi[(size_t)BS_ * QD_];
__device__ __nv_bfloat16 g_at_lo[(size_t)BS_ * QD_];
__device__ __nv_bfloat16 g_wqkvT_hi[(size_t)QKVD_ * H_];
__device__ __nv_bfloat16 g_wqkvT_lo[(size_t)QKVD_ * H_];
__device__ __nv_bfloat16 g_woT_hi[(size_t)H_ * QD_];
__device__ __nv_bfloat16 g_woT_lo[(size_t)H_ * QD_];

// split-bf16 operands (flash): rope'd Q (scaled) / K, transposed V
__device__ __nv_bfloat16 g_q_hi[(size_t)BS_ * QD_];
__device__ __nv_bfloat16 g_q_lo[(size_t)BS_ * QD_];
__device__ __nv_bfloat16 g_k_hi[(size_t)BS_ * KD_];
__device__ __nv_bfloat16 g_k_lo[(size_t)BS_ * KD_];
__device__ __nv_bfloat16 g_vt_hi[(size_t)B_ * NKV_ * HD_ * S_];
__device__ __nv_bfloat16 g_vt_lo[(size_t)B_ * NKV_ * HD_ * S_];

// ---------------------------------------------------------------------------
// PTX helpers (BASE target only — no sm_103a-suffixed instructions)
// ---------------------------------------------------------------------------
__device__ __forceinline__ uint32_t smem_u32(const void* p) {
  uint32_t a;
  asm("{ .reg .u64 t; cvta.to.shared.u64 t, %1; cvt.u32.u64 %0, t; }"
      : "=r"(a) : "l"(p));
  return a;
}
#define SWZ128(off) ((off) ^ (((off) >> 3) & 0x70))

__device__ __forceinline__ void cp_async16(uint32_t saddr, const void* gaddr) {
  asm volatile("cp.async.cg.shared.global [%0], [%1], 16;"
               :: "r"(saddr), "l"(gaddr));
}
#define CP_COMMIT() asm volatile("cp.async.commit_group;" ::: "memory")
#define CP_WAIT(n)  asm volatile("cp.async.wait_group %0;" :: "n"(n) : "memory")

__device__ __forceinline__ void ldsm_x4(uint32_t* r, uint32_t addr) {
  asm volatile("ldmatrix.sync.aligned.m8n8.x4.shared.b16 {%0,%1,%2,%3}, [%4];"
               : "=r"(r[0]), "=r"(r[1]), "=r"(r[2]), "=r"(r[3]) : "r"(addr));
}
__device__ __forceinline__ void mma_bf16(float* d, const uint32_t* a,
                                         const uint32_t* b) {
  asm volatile(
      "mma.sync.aligned.m16n8k16.row.col.f32.bf16.bf16.f32 "
      "{%0,%1,%2,%3}, {%4,%5,%6,%7}, {%8,%9}, {%0,%1,%2,%3};"
      : "+f"(d[0]), "+f"(d[1]), "+f"(d[2]), "+f"(d[3])
      : "r"(a[0]), "r"(a[1]), "r"(a[2]), "r"(a[3]), "r"(b[0]), "r"(b[1]));
}
__device__ __forceinline__ uint32_t pack_bf16x2(float x, float y) {
  uint32_t r;  // low half = x, high half = y
  asm("cvt.rn.bf16x2.f32 %0, %1, %2;" : "=r"(r) : "f"(y), "f"(x));
  return r;
}
__device__ __forceinline__ void split_pack(float x, float y,
                                           uint32_t& hi, uint32_t& lo) {
  uint32_t h = pack_bf16x2(x, y);
  float hx = __uint_as_float(h << 16);
  float hy = __uint_as_float(h & 0xFFFF0000u);
  lo = pack_bf16x2(x - hx, y - hy);
  hi = h;
}

// ---------------------------------------------------------------------------
// split conversions
// ---------------------------------------------------------------------------
__global__ void split_kernel(const float* __restrict__ X,
                             __nv_bfloat16* __restrict__ Hi,
                             __nv_bfloat16* __restrict__ Lo) {
  size_t i = ((size_t)blockIdx.x * blockDim.x + threadIdx.x) * 4;
  float4 v = *(const float4*)(X + i);
  __nv_bfloat162 h01 = __floats2bfloat162_rn(v.x, v.y);
  __nv_bfloat162 h23 = __floats2bfloat162_rn(v.z, v.w);
  float lx = v.x - __bfloat162float(h01.x);
  float ly = v.y - __bfloat162float(h01.y);
  float lz = v.z - __bfloat162float(h23.x);
  float lw = v.w - __bfloat162float(h23.y);
  *(__nv_bfloat162*)(Hi + i)     = h01;
  *(__nv_bfloat162*)(Hi + i + 2) = h23;
  *(__nv_bfloat162*)(Lo + i)     = __floats2bfloat162_rn(lx, ly);
  *(__nv_bfloat162*)(Lo + i + 2) = __floats2bfloat162_rn(lz, lw);
}

// W[K,N] fp32 -> T[N,K] bf16 hi/lo (transpose + split)
__global__ void transpose_split_kernel(const float* __restrict__ W,
                                       __nv_bfloat16* __restrict__ Thi,
                                       __nv_bfloat16* __restrict__ Tlo,
                                       int K, int N) {
  __shared__ float tile[32][33];
  int n0 = blockIdx.x * 32, k0 = blockIdx.y * 32;
  int tx = threadIdx.x, ty = threadIdx.y;  // 32 x 8
#pragma unroll
  for (int i = 0; i < 32; i += 8)
    tile[ty + i][tx] = W[(size_t)(k0 + ty + i) * N + n0 + tx];
  __syncthreads();
#pragma unroll
  for (int i = 0; i < 32; i += 8) {
    float v = tile[tx][ty + i];
    __nv_bfloat16 h = __float2bfloat16_rn(v);
    __nv_bfloat16 l = __float2bfloat16_rn(v - __bfloat162float(h));
    size_t o = (size_t)(n0 + ty + i) * K + k0 + tx;
    Thi[o] = h;
    Tlo[o] = l;
  }
}

// ---------------------------------------------------------------------------
// Warp-MMA split-bf16 GEMM: C[M,N] = A[M,K] @ T[N,K]^T
// CTA tile 256x128, 8 warps (64x64 each, 4x2), K chunks of 64,
// double-buffered cp.async. 3 products: Ahi*Bhi + Ahi*Blo + Alo*Bhi.
// ---------------------------------------------------------------------------
constexpr int AT_B      = 256 * 128;            // 32 KB per A half
constexpr int BT_B      = 128 * 128;            // 16 KB per B half
constexpr int STG_B     = 2 * AT_B + 2 * BT_B;  // 96 KB per stage
constexpr int GEMM_SMEM = 2 * STG_B;            // 192 KB

__global__ __launch_bounds__(256, 1) void wm_gemm_kernel(
    const __nv_bfloat16* __restrict__ Ahi, const __nv_bfloat16* __restrict__ Alo,
    const __nv_bfloat16* __restrict__ Bhi, const __nv_bfloat16* __restrict__ Blo,
    float* __restrict__ C, int M, int N, int K) {
  extern __shared__ char dsm[];
  const uint32_t sbase = smem_u32(dsm);

  const int tid = threadIdx.x;
  const int wid = tid >> 5, lane = tid & 31;
  const int m0 = blockIdx.y * 256, n0 = blockIdx.x * 128;
  const int m0w = (wid & 3) * 64;   // 4 M-subtiles
  const int n0w = (wid >> 2) * 64;  // 2 N-subtiles

  const int seg = tid & 7;
  const int rb  = tid >> 3;         // 0..31
  const size_t Kb = (size_t)K * 2;
  const char* pAhi = (const char*)Ahi + (size_t)(m0 + rb) * Kb + seg * 16;
  const char* pAlo = (const char*)Alo + (size_t)(m0 + rb) * Kb + seg * 16;
  const char* pBhi = (const char*)Bhi + (size_t)(n0 + rb) * Kb + seg * 16;
  const char* pBlo = (const char*)Blo + (size_t)(n0 + rb) * Kb + seg * 16;

  const int rr = lane & 7;
  const int jj = lane >> 3;
  const uint32_t a_row = (uint32_t)(m0w + ((jj & 1) << 3) + rr);
  const uint32_t a_seg = (uint32_t)((jj >> 1) << 4);
  const uint32_t b_row = (uint32_t)(n0w + ((jj >> 1) << 3) + rr);
  const uint32_t b_seg = (uint32_t)((jj & 1) << 4);

  float acc[4][8][4];
#pragma unroll
  for (int i = 0; i < 4; i++)
#pragma unroll
    for (int j = 0; j < 8; j++)
#pragma unroll
      for (int t = 0; t < 4; t++) acc[i][j][t] = 0.f;

  const int NC = K / 64;

  // prologue: chunk 0 -> stage 0
#pragma unroll
  for (int i = 0; i < 8; i++) {
    uint32_t so = SWZ128((uint32_t)((rb + 32 * i) * 128 + seg * 16));
    size_t go = (size_t)(32 * i) * Kb;
    cp_async16(sbase + so,        pAhi + go);
    cp_async16(sbase + AT_B + so, pAlo + go);
  }
#pragma unroll
  for (int i = 0; i < 4; i++) {
    uint32_t so = SWZ128((uint32_t)((rb + 32 * i) * 128 + seg * 16));
    size_t go = (size_t)(32 * i) * Kb;
    cp_async16(sbase + 2 * AT_B + so,        pBhi + go);
    cp_async16(sbase + 2 * AT_B + BT_B + so, pBlo + go);
  }
  CP_COMMIT();

  for (int c = 0; c < NC; c++) {
    if (c + 1 < NC) {
      const uint32_t sb = sbase + (uint32_t)((c + 1) & 1) * STG_B;
      const size_t kb = (size_t)(c + 1) * 128;
#pragma unroll
      for (int i = 0; i < 8; i++) {
        uint32_t so = SWZ128((uint32_t)((rb + 32 * i) * 128 + seg * 16));
        size_t go = (size_t)(32 * i) * Kb + kb;
        cp_async16(sb + so,        pAhi + go);
        cp_async16(sb + AT_B + so, pAlo + go);
      }
#pragma unroll
      for (int i = 0; i < 4; i++) {
        uint32_t so = SWZ128((uint32_t)((rb + 32 * i) * 128 + seg * 16));
        size_t go = (size_t)(32 * i) * Kb + kb;
        cp_async16(sb + 2 * AT_B + so,        pBhi + go);
        cp_async16(sb + 2 * AT_B + BT_B + so, pBlo + go);
      }
      CP_COMMIT();
      CP_WAIT(1);
    } else {
      CP_WAIT(0);
    }
    __syncthreads();

    const uint32_t sb   = sbase + (uint32_t)(c & 1) * STG_B;
    const uint32_t sAhi = sb;
    const uint32_t sAlo = sb + AT_B;
    const uint32_t sBhi = sb + 2 * AT_B;
    const uint32_t sBlo = sb + 2 * AT_B + BT_B;

#pragma unroll
    for (int kk = 0; kk < 4; kk++) {
      uint32_t ah[4][4], al[4][4], bh[4][4], bl[4][4];
      const uint32_t kbyte = (uint32_t)(kk * 32);
#pragma unroll
      for (int mt = 0; mt < 4; mt++) {
        uint32_t off = SWZ128((a_row + mt * 16) * 128 + kbyte + a_seg);
        ldsm_x4(ah[mt], sAhi + off);
        ldsm_x4(al[mt], sAlo + off);
      }
#pragma unroll
      for (int nt = 0; nt < 4; nt++) {
        uint32_t off = SWZ128((b_row + nt * 16) * 128 + kbyte + b_seg);
        ldsm_x4(bh[nt], sBhi + off);
        ldsm_x4(bl[nt], sBlo + off);
      }
#pragma unroll
      for (int mt = 0; mt < 4; mt++)
#pragma unroll
        for (int nt8 = 0; nt8 < 8; nt8++) {
          const int n16 = nt8 >> 1, hf = (nt8 & 1) * 2;
          mma_bf16(acc[mt][nt8], ah[mt], &bh[n16][hf]);
          mma_bf16(acc[mt][nt8], ah[mt], &bl[n16][hf]);
          mma_bf16(acc[mt][nt8], al[mt], &bh[n16][hf]);
        }
    }
    __syncthreads();
  }

  const int grp = lane >> 2;
  const int cq  = (lane & 3) * 2;
#pragma unroll
  for (int mt = 0; mt < 4; mt++) {
    const int row = m0 + m0w + mt * 16 + grp;
#pragma unroll
    for (int nt8 = 0; nt8 < 8; nt8++) {
      const int col = n0 + n0w + nt8 * 8 + cq;
      float* c0 = C + (size_t)row * N + col;
      float* c1 = C + (size_t)(row + 8) * N + col;
      *(float2*)c0 = make_float2(acc[mt][nt8][0], acc[mt][nt8][1]);
      *(float2*)c1 = make_float2(acc[mt][nt8][2], acc[mt][nt8][3]);
    }
  }
}

// ---------------------------------------------------------------------------
// RoPE + split to bf16 hi/lo from fused qkv buffer. Q gets softmax scale.
// ---------------------------------------------------------------------------
__global__ void rope_split_kernel(const float* __restrict__ qkv,
                                  const float* __restrict__ cosb,
                                  const float* __restrict__ sinb,
                                  __nv_bfloat16* __restrict__ qhi,
                                  __nv_bfloat16* __restrict__ qlo,
                                  __nv_bfloat16* __restrict__ khi,
                                  __nv_bfloat16* __restrict__ klo) {
  int gid = blockIdx.x * blockDim.x + threadIdx.x;
  int d = gid & 63;
  int t = gid >> 6;
  int hh = t % (NH_ + NKV_);
  int bs = t / (NH_ + NKV_);
  float c  = cosb[bs * HD_ + d];
  float sn = sinb[bs * HD_ + d];
  if (hh < NH_) {
    size_t src = (size_t)bs * QKVD_ + hh * HD_ + d;
    size_t off = (size_t)bs * QD_ + hh * HD_ + d;
    const float scale = 0.08838834764831845f;  // 1/sqrt(128)
    float x1 = qkv[src], x2 = qkv[src + 64];
    float y1 = (x1 * c - x2 * sn) * scale;
    float y2 = (x2 * c + x1 * sn) * scale;
    __nv_bfloat16 h1 = __float2bfloat16_rn(y1);
    __nv_bfloat16 h2 = __float2bfloat16_rn(y2);
    qhi[off]      = h1;
    qlo[off]      = __float2bfloat16_rn(y1 - __bfloat162float(h1));
    qhi[off + 64] = h2;
    qlo[off + 64] = __float2bfloat16_rn(y2 - __bfloat162float(h2));
  } else {
    int kvh = hh - NH_;
    size_t src = (size_t)bs * QKVD_ + QD_ + kvh * HD_ + d;
    size_t off = (size_t)bs * KD_ + kvh * HD_ + d;
    float x1 = qkv[src], x2 = qkv[src + 64];
    float y1 = x1 * c - x2 * sn;
    float y2 = x2 * c + x1 * sn;
    __nv_bfloat16 h1 = __float2bfloat16_rn(y1);
    __nv_bfloat16 h2 = __float2bfloat16_rn(y2);
    khi[off]      = h1;
    klo[off]      = __float2bfloat16_rn(y1 - __bfloat162float(h1));
    khi[off + 64] = h2;
    klo[off + 64] = __float2bfloat16_rn(y2 - __bfloat162float(h2));
  }
}

// V slice of qkv -> Vt [(b*NKV+kvh)*128+d][s] bf16 hi/lo
__global__ void vt_split_kernel(const float* __restrict__ qkv,
                                __nv_bfloat16* __restrict__ vthi,
                                __nv_bfloat16* __restrict__ vtlo) {
  __shared__ float tl[32][33];
  int s0 = blockIdx.x * 32, d0 = blockIdx.y * 32, bh = blockIdx.z;
  int b = bh >> 3, kvh = bh & 7;
  int tx = threadIdx.x, ty = threadIdx.y;  // 32 x 8
#pragma unroll
  for (int i = 0; i < 32; i += 8)
    tl[ty + i][tx] = qkv[(size_t)(b * S_ + s0 + ty + i) * QKVD_ +
                         QD_ + KD_ + kvh * HD_ + d0 + tx];
  __syncthreads();
#pragma unroll
  for (int i = 0; i < 32; i += 8) {
    float val = tl[tx][ty + i];  // s = s0+tx, d = d0+ty+i
    __nv_bfloat16 h = __float2bfloat16_rn(val);
    __nv_bfloat16 l = __float2bfloat16_rn(val - __bfloat162float(h));
    size_t o = ((size_t)bh * HD_ + d0 + ty + i) * S_ + s0 + tx;
    vthi[o] = h;
    vtlo[o] = l;
  }
}

// ---------------------------------------------------------------------------
// Flash attention, HMMA split-bf16. Writes split-bf16 output directly.
// BQ=128 (8 warps x m16), BKT=64, double-buffered K/V, Q resident.
// ---------------------------------------------------------------------------
constexpr int FLASH2_SMEM = 196608;

__global__ __launch_bounds__(256, 1) void flash_hmma_kernel(
    const __nv_bfloat16* __restrict__ Qhi_g, const __nv_bfloat16* __restrict__ Qlo_g,
    const __nv_bfloat16* __restrict__ Khi_g, const __nv_bfloat16* __restrict__ Klo_g,
    const __nv_bfloat16* __restrict__ Vthi_g, const __nv_bfloat16* __restrict__ Vtlo_g,
    __nv_bfloat16* __restrict__ Ohi_g, __nv_bfloat16* __restrict__ Olo_g) {
  extern __shared__ char sm[];
  const uint32_t sb = smem_u32(sm);
  const int qt = blockIdx.x, h = blockIdx.y, b = blockIdx.z;
  const int kvh = h >> 2;                 // n_rep = 4
  const int tid = threadIdx.x, wid = tid >> 5, lane = tid & 31;
  const int q0 = qt * 128;
  const int q0w = q0 + wid * 16;

  const uint32_t sQhi = sb;               // 2 chunks of 16KB (d halves)
  const uint32_t sQlo = sb + 32768;
  const uint32_t sKb  = sb + 65536;       // + buf*32768; hi chunks 0/8K, lo +16K
  const uint32_t sVb  = sb + 131072;      // + buf*32768; hi 0, lo +16K

  // ---- Q tile load (hi+lo) ----
  {
    const int seg = tid & 15, r0 = tid >> 4;
    const size_t qoff = ((size_t)(b * S_ + q0) * QD_ + h * HD_) * 2;
    const char* ph = (const char*)Qhi_g + qoff;
    const char* pl = (const char*)Qlo_g + qoff;
#pragma unroll
    for (int i = 0; i < 8; i++) {
      int r = r0 + i * 16;
      uint32_t off = ((seg >> 3) * 16384) +
                     SWZ128((uint32_t)(r * 128 + (seg & 7) * 16));
      size_t g = (size_t)r * (QD_ * 2) + seg * 16;
      cp_async16(sQhi + off, ph + g);
      cp_async16(sQlo + off, pl + g);
    }
  }
  CP_COMMIT();

  const int nkt = 2 * qt + 2;

  auto load_kv = [&](int kt, int buf) {
    const uint32_t sK = sKb + (uint32_t)buf * 32768;
    const uint32_t sV = sVb + (uint32_t)buf * 32768;
    {
      const int seg = tid & 15, r0 = tid >> 4;
      const size_t koff = ((size_t)(b * S_ + kt * 64) * KD_ + kvh * HD_) * 2;
      const char* ph = (const char*)Khi_g + koff;
      const char* pl = (const char*)Klo_g + koff;
#pragma unroll
      for (int i = 0; i < 4; i++) {
        int r = r0 + i * 16;
        uint32_t off = ((seg >> 3) * 8192) +
                       SWZ128((uint32_t)(r * 128 + (seg & 7) * 16));
        size_t g = (size_t)r * (KD_ * 2) + seg * 16;
        cp_async16(sK + off,         ph + g);
        cp_async16(sK + 16384 + off, pl + g);
      }
    }
    {
      const int seg = tid & 7, d0 = tid >> 3;
      const size_t voff = ((size_t)(b * NKV_ + kvh) * HD_ * S_ + (size_t)kt * 64) * 2;
      const char* ph = (const char*)Vthi_g + voff;
      const char* pl = (const char*)Vtlo_g + voff;
#pragma unroll
      for (int i = 0; i < 4; i++) {
        int d = d0 + i * 32;
        uint32_t off = SWZ128((uint32_t)(d * 128 + seg * 16));
        size_t g = (size_t)d * (S_ * 2) + seg * 16;
        cp_async16(sV + off,         ph + g);
        cp_async16(sV + 16384 + off, pl + g);
      }
    }
    CP_COMMIT();
  };

  load_kv(0, 0);

  // fragment addressing
  const int rr = lane & 7, jj = lane >> 3;
  const uint32_t a_row = (uint32_t)(wid * 16 + ((jj & 1) << 3) + rr);
  const uint32_t a_seg = (uint32_t)((jj >> 1) << 4);
  const uint32_t b_rw  = (uint32_t)(((jj >> 1) << 3) + rr);
  const uint32_t b_seg = (uint32_t)((jj & 1) << 4);

  float oa[16][4];
#pragma unroll
  for (int g = 0; g < 16; g++)
#pragma unroll
    for (int t = 0; t < 4; t++) oa[g][t] = 0.f;
  float m0 = -INFINITY, m1 = -INFINITY, l0 = 0.f, l1 = 0.f;

  for (int kt = 0; kt < nkt; kt++) {
    const int buf = kt & 1;
    if (kt + 1 < nkt) {
      load_kv(kt + 1, buf ^ 1);
      CP_WAIT(1);
    } else {
      CP_WAIT(0);
    }
    __syncthreads();

    if (kt * 64 <= q0w + 15) {  // tile intersects this warp's rows
      const uint32_t sK = sKb + (uint32_t)buf * 32768;
      const uint32_t sV = sVb + (uint32_t)buf * 32768;

      // ---- S = Q @ K^T (split-bf16, 3 products) ----
      float sa[8][4];
#pragma unroll
      for (int t = 0; t < 8; t++)
#pragma unroll
        for (int e = 0; e < 4; e++) sa[t][e] = 0.f;

#pragma unroll
      for (int kk = 0; kk < 8; kk++) {
        uint32_t ah[4], al[4];
        uint32_t qo = ((uint32_t)(kk >> 2) * 16384) +
                      SWZ128(a_row * 128 + (uint32_t)(kk & 3) * 32 + a_seg);
        ldsm_x4(ah, sQhi + qo);
        ldsm_x4(al, sQlo + qo);
#pragma unroll
        for (int nt = 0; nt < 4; nt++) {
          uint32_t bhf[4], blf[4];
          uint32_t ko = ((uint32_t)(kk >> 2) * 8192) +
                        SWZ128((b_rw + nt * 16) * 128 + (uint32_t)(kk & 3) * 32 + b_seg);
          ldsm_x4(bhf, sK + ko);
          ldsm_x4(blf, sK + 16384 + ko);
          mma_bf16(sa[nt * 2],     ah, &bhf[0]);
          mma_bf16(sa[nt * 2],     ah, &blf[0]);
          mma_bf16(sa[nt * 2],     al, &bhf[0]);
          mma_bf16(sa[nt * 2 + 1], ah, &bhf[2]);
          mma_bf16(sa[nt * 2 + 1], ah, &blf[2]);
          mma_bf16(sa[nt * 2 + 1], al, &bhf[2]);
        }
      }

      // ---- causal mask ----
      if (kt * 64 + 63 > q0w) {
        int r0g = q0w + (lane >> 2);
#pragma unroll
        for (int t = 0; t < 8; t++) {
          int c0 = kt * 64 + t * 8 + ((lane & 3) << 1);
          if (c0     > r0g)     sa[t][0] = -1e30f;
          if (c0 + 1 > r0g)     sa[t][1] = -1e30f;
          if (c0     > r0g + 8) sa[t][2] = -1e30f;
          if (c0 + 1 > r0g + 8) sa[t][3] = -1e30f;
        }
      }

      // ---- online softmax (rows r, r+8) ----
      float mx0 = -INFINITY, mx1 = -INFINITY;
#pragma unroll
      for (int t = 0; t < 8; t++) {
        mx0 = fmaxf(mx0, fmaxf(sa[t][0], sa[t][1]));
        mx1 = fmaxf(mx1, fmaxf(sa[t][2], sa[t][3]));
      }
      mx0 = fmaxf(mx0, __shfl_xor_sync(0xffffffffu, mx0, 1));
      mx0 = fmaxf(mx0, __shfl_xor_sync(0xffffffffu, mx0, 2));
      mx1 = fmaxf(mx1, __shfl_xor_sync(0xffffffffu, mx1, 1));
      mx1 = fmaxf(mx1, __shfl_xor_sync(0xffffffffu, mx1, 2));
      float mn0 = fmaxf(m0, mx0), mn1 = fmaxf(m1, mx1);
      float f0 = __expf(m0 - mn0), f1 = __expf(m1 - mn1);
      m0 = mn0; m1 = mn1;
      float s0 = 0.f, s1 = 0.f;
#pragma unroll
      for (int t = 0; t < 8; t++) {
        sa[t][0] = __expf(sa[t][0] - mn0);
        sa[t][1] = __expf(sa[t][1] - mn0);
        sa[t][2] = __expf(sa[t][2] - mn1);
        sa[t][3] = __expf(sa[t][3] - mn1);
        s0 += sa[t][0] + sa[t][1];
        s1 += sa[t][2] + sa[t][3];
      }
      s0 += __shfl_xor_sync(0xffffffffu, s0, 1);
      s0 += __shfl_xor_sync(0xffffffffu, s0, 2);
      s1 += __shfl_xor_sync(0xffffffffu, s1, 1);
      s1 += __shfl_xor_sync(0xffffffffu, s1, 2);
      l0 = l0 * f0 + s0;
      l1 = l1 * f1 + s1;
#pragma unroll
      for (int g = 0; g < 16; g++) {
        oa[g][0] *= f0; oa[g][1] *= f0;
        oa[g][2] *= f1; oa[g][3] *= f1;
      }

      // ---- O += P @ V  (P in registers, split; V split) ----
#pragma unroll
      for (int kk2 = 0; kk2 < 4; kk2++) {
        uint32_t ahp[4], alp[4];
        split_pack(sa[2 * kk2][0],     sa[2 * kk2][1],     ahp[0], alp[0]);
        split_pack(sa[2 * kk2][2],     sa[2 * kk2][3],     ahp[1], alp[1]);
        split_pack(sa[2 * kk2 + 1][0], sa[2 * kk2 + 1][1], ahp[2], alp[2]);
        split_pack(sa[2 * kk2 + 1][2], sa[2 * kk2 + 1][3], ahp[3], alp[3]);
#pragma unroll
        for (int g7 = 0; g7 < 8; g7++) {
          uint32_t bvh[4], bvl[4];
          uint32_t vo = SWZ128((g7 * 16 + b_rw) * 128 + (uint32_t)kk2 * 32 + b_seg);
          ldsm_x4(bvh, sV + vo);
          ldsm_x4(bvl, sV + 16384 + vo);
          mma_bf16(oa[g7 * 2],     ahp, &bvh[0]);
          mma_bf16(oa[g7 * 2],     ahp, &bvl[0]);
          mma_bf16(oa[g7 * 2],     alp, &bvh[0]);
          mma_bf16(oa[g7 * 2 + 1], ahp, &bvh[2]);
          mma_bf16(oa[g7 * 2 + 1], ahp, &bvl[2]);
          mma_bf16(oa[g7 * 2 + 1], alp, &bvh[2]);
        }
      }
    }
    __syncthreads();
  }

  // ---- epilogue: normalize and store split-bf16 directly ----
  {
    float inv0 = 1.f / l0, inv1 = 1.f / l1;
    const size_t r0 = (size_t)(b * S_ + q0w + (lane >> 2)) * QD_;
    const size_t r1 = r0 + (size_t)8 * QD_;
    const int cb = h * HD_ + ((lane & 3) << 1);
#pragma unroll
    for (int g = 0; g < 16; g++) {
      uint32_t hi, lo;
      split_pack(oa[g][0] * inv0, oa[g][1] * inv0, hi, lo);
      *(uint32_t*)(Ohi_g + r0 + cb + g * 8) = hi;
      *(uint32_t*)(Olo_g + r0 + cb + g * 8) = lo;
      split_pack(oa[g][2] * inv1, oa[g][3] * inv1, hi, lo);
      *(uint32_t*)(Ohi_g + r1 + cb + g * 8) = hi;
      *(uint32_t*)(Olo_g + r1 + cb + g * 8) = lo;
    }
  }
}

// ---------------------------------------------------------------------------
extern "C" void kernel_launch(void* const* d_in, const int* in_sizes, int n_in,
                              void* d_out, int out_size) {
  const float* hs   = (const float*)d_in[0];
  const float* cosb = (const float*)d_in[1];
  const float* sinb = (const float*)d_in[2];
  const float* wq   = (const float*)d_in[3];
  const float* wk   = (const float*)d_in[4];
  const float* wv   = (const float*)d_in[5];
  const float* wo   = (const float*)d_in[6];
  float* out = (float*)d_out;

  float* qkv;
  cudaGetSymbolAddress((void**)&qkv, g_qkv);

  __nv_bfloat16 *hshi, *hslo, *athi, *atlo;
  __nv_bfloat16 *wqkvh, *wqkvl, *woh, *wol;
  __nv_bfloat16 *qhi, *qlo, *khi, *klo, *vthi, *vtlo;
  cudaGetSymbolAddress((void**)&hshi, g_hs_hi);
  cudaGetSymbolAddress((void**)&hslo, g_hs_lo);
  cudaGetSymbolAddress((void**)&athi, g_at_hi);
  cudaGetSymbolAddress((void**)&atlo, g_at_lo);
  cudaGetSymbolAddress((void**)&wqkvh, g_wqkvT_hi);
  cudaGetSymbolAddress((void**)&wqkvl, g_wqkvT_lo);
  cudaGetSymbolAddress((void**)&woh, g_woT_hi);
  cudaGetSymbolAddress((void**)&wol, g_woT_lo);
  cudaGetSymbolAddress((void**)&qhi, g_q_hi);
  cudaGetSymbolAddress((void**)&qlo, g_q_lo);
  cudaGetSymbolAddress((void**)&khi, g_k_hi);
  cudaGetSymbolAddress((void**)&klo, g_k_lo);
  cudaGetSymbolAddress((void**)&vthi, g_vt_hi);
  cudaGetSymbolAddress((void**)&vtlo, g_vt_lo);

  cudaFuncSetAttribute(wm_gemm_kernel,
                       cudaFuncAttributeMaxDynamicSharedMemorySize, GEMM_SMEM);
  cudaFuncSetAttribute(flash_hmma_kernel,
                       cudaFuncAttributeMaxDynamicSharedMemorySize, FLASH2_SMEM);

  // split hidden states; transpose+split weights (wq|wk|wv fused rows)
  split_kernel<<<(size_t)BS_ * H_ / 1024, 256>>>(hs, hshi, hslo);
  transpose_split_kernel<<<dim3(QD_ / 32, H_ / 32), dim3(32, 8)>>>(
      wq, wqkvh, wqkvl, H_, QD_);
  transpose_split_kernel<<<dim3(KD_ / 32, H_ / 32), dim3(32, 8)>>>(
      wk, wqkvh + (size_t)QD_ * H_, wqkvl + (size_t)QD_ * H_, H_, KD_);
  transpose_split_kernel<<<dim3(KD_ / 32, H_ / 32), dim3(32, 8)>>>(
      wv, wqkvh + (size_t)(QD_ + KD_) * H_, wqkvl + (size_t)(QD_ + KD_) * H_,
      H_, KD_);
  transpose_split_kernel<<<dim3(H_ / 32, QD_ / 32), dim3(32, 8)>>>(
      wo, woh, wol, QD_, H_);

  // fused QKV projection (warp MMA, 256x128 tiles)
  wm_gemm_kernel<<<dim3(QKVD_ / 128, BS_ / 256), 256, GEMM_SMEM>>>(
      hshi, hslo, wqkvh, wqkvl, qkv, BS_, QKVD_, H_);

  // RoPE + split (scale folded into Q); V transpose + split
  {
    int total = B_ * S_ * (NH_ + NKV_) * 64;
    rope_split_kernel<<<total / 256, 256>>>(qkv, cosb, sinb, qhi, qlo, khi, klo);
  }
  vt_split_kernel<<<dim3(S_ / 32, HD_ / 32, B_ * NKV_), dim3(32, 8)>>>(
      qkv, vthi, vtlo);

  // Causal GQA flash attention (HMMA split-bf16), writes split output
  flash_hmma_kernel<<<dim3(S_ / 128, NH_, B_), 256, FLASH2_SMEM>>>(
      qhi, qlo, khi, klo, vthi, vtlo, athi, atlo);

  // O projection
  wm_gemm_kernel<<<dim3(H_ / 128, BS_ / 256), 256, GEMM_SMEM>>>(
      athi, atlo, woh, wol, out, BS_, H_, H_);
}

// round 14
// speedup vs baseline: 1.0558x; 1.0558x over previous
#include <cuda_runtime.h>
#include <cuda_bf16.h>
#include <math.h>
#include <stdint.h>

// Problem constants
constexpr int B_   = 2;
constexpr int S_   = 2048;
constexpr int H_   = 4096;
constexpr int NH_  = 32;
constexpr int NKV_ = 8;
constexpr int HD_  = 128;
constexpr int BS_  = B_ * S_;        // 4096 rows
constexpr int QD_  = NH_ * HD_;      // 4096
constexpr int KD_  = NKV_ * HD_;     // 1024
constexpr int QKVD_ = QD_ + 2 * KD_; // 6144

// ---------------------------------------------------------------------------
// Scratch (device globals; no allocation allowed)
// ---------------------------------------------------------------------------
__device__ float g_qkv[(size_t)BS_ * QKVD_];   // fused QKV GEMM out (fp32)

// split-bf16 operands (GEMM)
__device__ __nv_bfloat16 g_hs_hi[(size_t)BS_ * H_];
__device__ __nv_bfloat16 g_hs_lo[(size_t)BS_ * H_];
__device__ __nv_bfloat16 g_at_hi[(size_t)BS_ * QD_];
__device__ __nv_bfloat16 g_at_lo[(size_t)BS_ * QD_];
__device__ __nv_bfloat16 g_wqkvT_hi[(size_t)QKVD_ * H_];
__device__ __nv_bfloat16 g_wqkvT_lo[(size_t)QKVD_ * H_];
__device__ __nv_bfloat16 g_woT_hi[(size_t)H_ * QD_];
__device__ __nv_bfloat16 g_woT_lo[(size_t)H_ * QD_];

// split-bf16 operands (flash): rope'd Q (scaled) / K, transposed V
__device__ __nv_bfloat16 g_q_hi[(size_t)BS_ * QD_];
__device__ __nv_bfloat16 g_q_lo[(size_t)BS_ * QD_];
__device__ __nv_bfloat16 g_k_hi[(size_t)BS_ * KD_];
__device__ __nv_bfloat16 g_k_lo[(size_t)BS_ * KD_];
__device__ __nv_bfloat16 g_vt_hi[(size_t)B_ * NKV_ * HD_ * S_];
__device__ __nv_bfloat16 g_vt_lo[(size_t)B_ * NKV_ * HD_ * S_];

// ---------------------------------------------------------------------------
// PTX helpers (BASE target only — no sm_103a-suffixed instructions)
// ---------------------------------------------------------------------------
__device__ __forceinline__ uint32_t smem_u32(const void* p) {
  uint32_t a;
  asm("{ .reg .u64 t; cvta.to.shared.u64 t, %1; cvt.u32.u64 %0, t; }"
      : "=r"(a) : "l"(p));
  return a;
}
#define SWZ128(off) ((off) ^ (((off) >> 3) & 0x70))

__device__ __forceinline__ void cp_async16(uint32_t saddr, const void* gaddr) {
  asm volatile("cp.async.cg.shared.global [%0], [%1], 16;"
               :: "r"(saddr), "l"(gaddr));
}
#define CP_COMMIT() asm volatile("cp.async.commit_group;" ::: "memory")
#define CP_WAIT(n)  asm volatile("cp.async.wait_group %0;" :: "n"(n) : "memory")

__device__ __forceinline__ void ldsm_x4(uint32_t* r, uint32_t addr) {
  asm volatile("ldmatrix.sync.aligned.m8n8.x4.shared.b16 {%0,%1,%2,%3}, [%4];"
               : "=r"(r[0]), "=r"(r[1]), "=r"(r[2]), "=r"(r[3]) : "r"(addr));
}
__device__ __forceinline__ void mma_bf16(float* d, const uint32_t* a,
                                         const uint32_t* b) {
  asm volatile(
      "mma.sync.aligned.m16n8k16.row.col.f32.bf16.bf16.f32 "
      "{%0,%1,%2,%3}, {%4,%5,%6,%7}, {%8,%9}, {%0,%1,%2,%3};"
      : "+f"(d[0]), "+f"(d[1]), "+f"(d[2]), "+f"(d[3])
      : "r"(a[0]), "r"(a[1]), "r"(a[2]), "r"(a[3]), "r"(b[0]), "r"(b[1]));
}
__device__ __forceinline__ uint32_t pack_bf16x2(float x, float y) {
  uint32_t r;  // low half = x, high half = y
  asm("cvt.rn.bf16x2.f32 %0, %1, %2;" : "=r"(r) : "f"(y), "f"(x));
  return r;
}
__device__ __forceinline__ void split_pack(float x, float y,
                                           uint32_t& hi, uint32_t& lo) {
  uint32_t h = pack_bf16x2(x, y);
  float hx = __uint_as_float(h << 16);
  float hy = __uint_as_float(h & 0xFFFF0000u);
  lo = pack_bf16x2(x - hx, y - hy);
  hi = h;
}

// ---------------------------------------------------------------------------
// split conversions
// ---------------------------------------------------------------------------
__global__ void split_kernel(const float* __restrict__ X,
                             __nv_bfloat16* __restrict__ Hi,
                             __nv_bfloat16* __restrict__ Lo) {
  size_t i = ((size_t)blockIdx.x * blockDim.x + threadIdx.x) * 4;
  float4 v = *(const float4*)(X + i);
  __nv_bfloat162 h01 = __floats2bfloat162_rn(v.x, v.y);
  __nv_bfloat162 h23 = __floats2bfloat162_rn(v.z, v.w);
  float lx = v.x - __bfloat162float(h01.x);
  float ly = v.y - __bfloat162float(h01.y);
  float lz = v.z - __bfloat162float(h23.x);
  float lw = v.w - __bfloat162float(h23.y);
  *(__nv_bfloat162*)(Hi + i)     = h01;
  *(__nv_bfloat162*)(Hi + i + 2) = h23;
  *(__nv_bfloat162*)(Lo + i)     = __floats2bfloat162_rn(lx, ly);
  *(__nv_bfloat162*)(Lo + i + 2) = __floats2bfloat162_rn(lz, lw);
}

// W[K,N] fp32 -> T[N,K] bf16 hi/lo (transpose + split)
__global__ void transpose_split_kernel(const float* __restrict__ W,
                                       __nv_bfloat16* __restrict__ Thi,
                                       __nv_bfloat16* __restrict__ Tlo,
                                       int K, int N) {
  __shared__ float tile[32][33];
  int n0 = blockIdx.x * 32, k0 = blockIdx.y * 32;
  int tx = threadIdx.x, ty = threadIdx.y;  // 32 x 8
#pragma unroll
  for (int i = 0; i < 32; i += 8)
    tile[ty + i][tx] = W[(size_t)(k0 + ty + i) * N + n0 + tx];
  __syncthreads();
#pragma unroll
  for (int i = 0; i < 32; i += 8) {
    float v = tile[tx][ty + i];
    __nv_bfloat16 h = __float2bfloat16_rn(v);
    __nv_bfloat16 l = __float2bfloat16_rn(v - __bfloat162float(h));
    size_t o = (size_t)(n0 + ty + i) * K + k0 + tx;
    Thi[o] = h;
    Tlo[o] = l;
  }
}

// ---------------------------------------------------------------------------
// Warp-MMA split-bf16 GEMM: C[M,N] = A[M,K] @ T[N,K]^T   (R10 config)
// 128x128 tile/CTA, 8 warps (64x32 each), K chunks of 64, double-buffered
// cp.async. 3 products per chunk: Ahi*Bhi + Ahi*Blo + Alo*Bhi.
// ---------------------------------------------------------------------------
constexpr int TILE_B    = 128 * 128;
constexpr int STAGE_B   = 4 * TILE_B;
constexpr int GEMM_SMEM = 2 * STAGE_B + 1024;

__global__ __launch_bounds__(256) void wm_gemm_kernel(
    const __nv_bfloat16* __restrict__ Ahi, const __nv_bfloat16* __restrict__ Alo,
    const __nv_bfloat16* __restrict__ Bhi, const __nv_bfloat16* __restrict__ Blo,
    float* __restrict__ C, int M, int N, int K) {
  extern __shared__ char dsm[];
  const uint32_t sbase = (smem_u32(dsm) + 1023u) & ~1023u;

  const int tid = threadIdx.x;
  const int wid = tid >> 5, lane = tid & 31;
  const int m0 = blockIdx.y * 128, n0 = blockIdx.x * 128;
  const int m0w = (wid & 1) * 64;
  const int n0w = (wid >> 1) * 32;

  const int seg = tid & 7;
  const int rb  = tid >> 3;
  const size_t Kb = (size_t)K * 2;
  const char* pAhi = (const char*)Ahi + (size_t)(m0 + rb) * Kb + seg * 16;
  const char* pAlo = (const char*)Alo + (size_t)(m0 + rb) * Kb + seg * 16;
  const char* pBhi = (const char*)Bhi + (size_t)(n0 + rb) * Kb + seg * 16;
  const char* pBlo = (const char*)Blo + (size_t)(n0 + rb) * Kb + seg * 16;

  const int rr = lane & 7;
  const int jj = lane >> 3;
  const uint32_t a_row = (uint32_t)(m0w + ((jj & 1) << 3) + rr);
  const uint32_t a_seg = (uint32_t)((jj >> 1) << 4);
  const uint32_t b_row = (uint32_t)(n0w + ((jj >> 1) << 3) + rr);
  const uint32_t b_seg = (uint32_t)((jj & 1) << 4);

  float acc[4][4][4];
#pragma unroll
  for (int i = 0; i < 4; i++)
#pragma unroll
    for (int j = 0; j < 4; j++)
#pragma unroll
      for (int t = 0; t < 4; t++) acc[i][j][t] = 0.f;

  const int NC = K / 64;

#pragma unroll
  for (int i = 0; i < 4; i++) {
    uint32_t so = SWZ128((uint32_t)((rb + 32 * i) * 128 + seg * 16));
    size_t go = (size_t)(32 * i) * Kb;
    cp_async16(sbase + so,              pAhi + go);
    cp_async16(sbase + TILE_B + so,     pAlo + go);
    cp_async16(sbase + 2 * TILE_B + so, pBhi + go);
    cp_async16(sbase + 3 * TILE_B + so, pBlo + go);
  }
  CP_COMMIT();

  for (int c = 0; c < NC; c++) {
    if (c + 1 < NC) {
      const uint32_t sb = sbase + (uint32_t)((c + 1) & 1) * STAGE_B;
      const size_t kb = (size_t)(c + 1) * 128;
#pragma unroll
      for (int i = 0; i < 4; i++) {
        uint32_t so = SWZ128((uint32_t)((rb + 32 * i) * 128 + seg * 16));
        size_t go = (size_t)(32 * i) * Kb + kb;
        cp_async16(sb + so,              pAhi + go);
        cp_async16(sb + TILE_B + so,     pAlo + go);
        cp_async16(sb + 2 * TILE_B + so, pBhi + go);
        cp_async16(sb + 3 * TILE_B + so, pBlo + go);
      }
      CP_COMMIT();
      CP_WAIT(1);
    } else {
      CP_WAIT(0);
    }
    __syncthreads();

    const uint32_t sb   = sbase + (uint32_t)(c & 1) * STAGE_B;
    const uint32_t sAhi = sb;
    const uint32_t sAlo = sb + TILE_B;
    const uint32_t sBhi = sb + 2 * TILE_B;
    const uint32_t sBlo = sb + 3 * TILE_B;

#pragma unroll
    for (int kk = 0; kk < 4; kk++) {
      uint32_t ah[4][4], al[4][4], bh[2][4], bl[2][4];
      const uint32_t kbyte = (uint32_t)(kk * 32);
#pragma unroll
      for (int mt = 0; mt < 4; mt++) {
        uint32_t off = SWZ128((a_row + mt * 16) * 128 + kbyte + a_seg);
        ldsm_x4(ah[mt], sAhi + off);
        ldsm_x4(al[mt], sAlo + off);
      }
#pragma unroll
      for (int nt = 0; nt < 2; nt++) {
        uint32_t off = SWZ128((b_row + nt * 16) * 128 + kbyte + b_seg);
        ldsm_x4(bh[nt], sBhi + off);
        ldsm_x4(bl[nt], sBlo + off);
      }
#pragma unroll
      for (int mt = 0; mt < 4; mt++)
#pragma unroll
        for (int nt8 = 0; nt8 < 4; nt8++) {
          const int n16 = nt8 >> 1, hf = (nt8 & 1) * 2;
          mma_bf16(acc[mt][nt8], ah[mt], &bh[n16][hf]);
          mma_bf16(acc[mt][nt8], ah[mt], &bl[n16][hf]);
          mma_bf16(acc[mt][nt8], al[mt], &bh[n16][hf]);
        }
    }
    __syncthreads();
  }

  const int grp = lane >> 2;
  const int cq  = (lane & 3) * 2;
#pragma unroll
  for (int mt = 0; mt < 4; mt++) {
    const int row = m0 + m0w + mt * 16 + grp;
#pragma unroll
    for (int nt8 = 0; nt8 < 4; nt8++) {
      const int col = n0 + n0w + nt8 * 8 + cq;
      float* c0 = C + (size_t)row * N + col;
      float* c1 = C + (size_t)(row + 8) * N + col;
      *(float2*)c0 = make_float2(acc[mt][nt8][0], acc[mt][nt8][1]);
      *(float2*)c1 = make_float2(acc[mt][nt8][2], acc[mt][nt8][3]);
    }
  }
}

// ---------------------------------------------------------------------------
// RoPE + split to bf16 hi/lo from fused qkv buffer. Q gets softmax scale.
// ---------------------------------------------------------------------------
__global__ void rope_split_kernel(const float* __restrict__ qkv,
                                  const float* __restrict__ cosb,
                                  const float* __restrict__ sinb,
                                  __nv_bfloat16* __restrict__ qhi,
                                  __nv_bfloat16* __restrict__ qlo,
                                  __nv_bfloat16* __restrict__ khi,
                                  __nv_bfloat16* __restrict__ klo) {
  int gid = blockIdx.x * blockDim.x + threadIdx.x;
  int d = gid & 63;
  int t = gid >> 6;
  int hh = t % (NH_ + NKV_);
  int bs = t / (NH_ + NKV_);
  float c  = cosb[bs * HD_ + d];
  float sn = sinb[bs * HD_ + d];
  if (hh < NH_) {
    size_t src = (size_t)bs * QKVD_ + hh * HD_ + d;
    size_t off = (size_t)bs * QD_ + hh * HD_ + d;
    const float scale = 0.08838834764831845f;  // 1/sqrt(128)
    float x1 = qkv[src], x2 = qkv[src + 64];
    float y1 = (x1 * c - x2 * sn) * scale;
    float y2 = (x2 * c + x1 * sn) * scale;
    __nv_bfloat16 h1 = __float2bfloat16_rn(y1);
    __nv_bfloat16 h2 = __float2bfloat16_rn(y2);
    qhi[off]      = h1;
    qlo[off]      = __float2bfloat16_rn(y1 - __bfloat162float(h1));
    qhi[off + 64] = h2;
    qlo[off + 64] = __float2bfloat16_rn(y2 - __bfloat162float(h2));
  } else {
    int kvh = hh - NH_;
    size_t src = (size_t)bs * QKVD_ + QD_ + kvh * HD_ + d;
    size_t off = (size_t)bs * KD_ + kvh * HD_ + d;
    float x1 = qkv[src], x2 = qkv[src + 64];
    float y1 = x1 * c - x2 * sn;
    float y2 = x2 * c + x1 * sn;
    __nv_bfloat16 h1 = __float2bfloat16_rn(y1);
    __nv_bfloat16 h2 = __float2bfloat16_rn(y2);
    khi[off]      = h1;
    klo[off]      = __float2bfloat16_rn(y1 - __bfloat162float(h1));
    khi[off + 64] = h2;
    klo[off + 64] = __float2bfloat16_rn(y2 - __bfloat162float(h2));
  }
}

// V slice of qkv -> Vt [(b*NKV+kvh)*128+d][s] bf16 hi/lo
__global__ void vt_split_kernel(const float* __restrict__ qkv,
                                __nv_bfloat16* __restrict__ vthi,
                                __nv_bfloat16* __restrict__ vtlo) {
  __shared__ float tl[32][33];
  int s0 = blockIdx.x * 32, d0 = blockIdx.y * 32, bh = blockIdx.z;
  int b = bh >> 3, kvh = bh & 7;
  int tx = threadIdx.x, ty = threadIdx.y;  // 32 x 8
#pragma unroll
  for (int i = 0; i < 32; i += 8)
    tl[ty + i][tx] = qkv[(size_t)(b * S_ + s0 + ty + i) * QKVD_ +
                         QD_ + KD_ + kvh * HD_ + d0 + tx];
  __syncthreads();
#pragma unroll
  for (int i = 0; i < 32; i += 8) {
    float val = tl[tx][ty + i];  // s = s0+tx, d = d0+ty+i
    __nv_bfloat16 h = __float2bfloat16_rn(val);
    __nv_bfloat16 l = __float2bfloat16_rn(val - __bfloat162float(h));
    size_t o = ((size_t)bh * HD_ + d0 + ty + i) * S_ + s0 + tx;
    vthi[o] = h;
    vtlo[o] = l;
  }
}

// ---------------------------------------------------------------------------
// Flash attention, HMMA split-bf16. Writes split-bf16 output directly.
// BQ=128 (8 warps x m16), BKT=64, double-buffered K/V, Q resident.
// ---------------------------------------------------------------------------
constexpr int FLASH2_SMEM = 196608;

__global__ __launch_bounds__(256, 1) void flash_hmma_kernel(
    const __nv_bfloat16* __restrict__ Qhi_g, const __nv_bfloat16* __restrict__ Qlo_g,
    const __nv_bfloat16* __restrict__ Khi_g, const __nv_bfloat16* __restrict__ Klo_g,
    const __nv_bfloat16* __restrict__ Vthi_g, const __nv_bfloat16* __restrict__ Vtlo_g,
    __nv_bfloat16* __restrict__ Ohi_g, __nv_bfloat16* __restrict__ Olo_g) {
  extern __shared__ char sm[];
  const uint32_t sb = smem_u32(sm);
  const int qt = blockIdx.x, h = blockIdx.y, b = blockIdx.z;
  const int kvh = h >> 2;                 // n_rep = 4
  const int tid = threadIdx.x, wid = tid >> 5, lane = tid & 31;
  const int q0 = qt * 128;
  const int q0w = q0 + wid * 16;

  const uint32_t sQhi = sb;               // 2 chunks of 16KB (d halves)
  const uint32_t sQlo = sb + 32768;
  const uint32_t sKb  = sb + 65536;       // + buf*32768; hi chunks 0/8K, lo +16K
  const uint32_t sVb  = sb + 131072;      // + buf*32768; hi 0, lo +16K

  // ---- Q tile load (hi+lo) ----
  {
    const int seg = tid & 15, r0 = tid >> 4;
    const size_t qoff = ((size_t)(b * S_ + q0) * QD_ + h * HD_) * 2;
    const char* ph = (const char*)Qhi_g + qoff;
    const char* pl = (const char*)Qlo_g + qoff;
#pragma unroll
    for (int i = 0; i < 8; i++) {
      int r = r0 + i * 16;
      uint32_t off = ((seg >> 3) * 16384) +
                     SWZ128((uint32_t)(r * 128 + (seg & 7) * 16));
      size_t g = (size_t)r * (QD_ * 2) + seg * 16;
      cp_async16(sQhi + off, ph + g);
      cp_async16(sQlo + off, pl + g);
    }
  }
  CP_COMMIT();

  const int nkt = 2 * qt + 2;

  auto load_kv = [&](int kt, int buf) {
    const uint32_t sK = sKb + (uint32_t)buf * 32768;
    const uint32_t sV = sVb + (uint32_t)buf * 32768;
    {
      const int seg = tid & 15, r0 = tid >> 4;
      const size_t koff = ((size_t)(b * S_ + kt * 64) * KD_ + kvh * HD_) * 2;
      const char* ph = (const char*)Khi_g + koff;
      const char* pl = (const char*)Klo_g + koff;
#pragma unroll
      for (int i = 0; i < 4; i++) {
        int r = r0 + i * 16;
        uint32_t off = ((seg >> 3) * 8192) +
                       SWZ128((uint32_t)(r * 128 + (seg & 7) * 16));
        size_t g = (size_t)r * (KD_ * 2) + seg * 16;
        cp_async16(sK + off,         ph + g);
        cp_async16(sK + 16384 + off, pl + g);
      }
    }
    {
      const int seg = tid & 7, d0 = tid >> 3;
      const size_t voff = ((size_t)(b * NKV_ + kvh) * HD_ * S_ + (size_t)kt * 64) * 2;
      const char* ph = (const char*)Vthi_g + voff;
      const char* pl = (const char*)Vtlo_g + voff;
#pragma unroll
      for (int i = 0; i < 4; i++) {
        int d = d0 + i * 32;
        uint32_t off = SWZ128((uint32_t)(d * 128 + seg * 16));
        size_t g = (size_t)d * (S_ * 2) + seg * 16;
        cp_async16(sV + off,         ph + g);
        cp_async16(sV + 16384 + off, pl + g);
      }
    }
    CP_COMMIT();
  };

  load_kv(0, 0);

  // fragment addressing
  const int rr = lane & 7, jj = lane >> 3;
  const uint32_t a_row = (uint32_t)(wid * 16 + ((jj & 1) << 3) + rr);
  const uint32_t a_seg = (uint32_t)((jj >> 1) << 4);
  const uint32_t b_rw  = (uint32_t)(((jj >> 1) << 3) + rr);
  const uint32_t b_seg = (uint32_t)((jj & 1) << 4);

  float oa[16][4];
#pragma unroll
  for (int g = 0; g < 16; g++)
#pragma unroll
    for (int t = 0; t < 4; t++) oa[g][t] = 0.f;
  float m0 = -INFINITY, m1 = -INFINITY, l0 = 0.f, l1 = 0.f;

  for (int kt = 0; kt < nkt; kt++) {
    const int buf = kt & 1;
    if (kt + 1 < nkt) {
      load_kv(kt + 1, buf ^ 1);
      CP_WAIT(1);
    } else {
      CP_WAIT(0);
    }
    __syncthreads();

    if (kt * 64 <= q0w + 15) {  // tile intersects this warp's rows
      const uint32_t sK = sKb + (uint32_t)buf * 32768;
      const uint32_t sV = sVb + (uint32_t)buf * 32768;

      // ---- S = Q @ K^T (split-bf16, 3 products) ----
      float sa[8][4];
#pragma unroll
      for (int t = 0; t < 8; t++)
#pragma unroll
        for (int e = 0; e < 4; e++) sa[t][e] = 0.f;

#pragma unroll
      for (int kk = 0; kk < 8; kk++) {
        uint32_t ah[4], al[4];
        uint32_t qo = ((uint32_t)(kk >> 2) * 16384) +
                      SWZ128(a_row * 128 + (uint32_t)(kk & 3) * 32 + a_seg);
        ldsm_x4(ah, sQhi + qo);
        ldsm_x4(al, sQlo + qo);
#pragma unroll
        for (int nt = 0; nt < 4; nt++) {
          uint32_t bhf[4], blf[4];
          uint32_t ko = ((uint32_t)(kk >> 2) * 8192) +
                        SWZ128((b_rw + nt * 16) * 128 + (uint32_t)(kk & 3) * 32 + b_seg);
          ldsm_x4(bhf, sK + ko);
          ldsm_x4(blf, sK + 16384 + ko);
          mma_bf16(sa[nt * 2],     ah, &bhf[0]);
          mma_bf16(sa[nt * 2],     ah, &blf[0]);
          mma_bf16(sa[nt * 2],     al, &bhf[0]);
          mma_bf16(sa[nt * 2 + 1], ah, &bhf[2]);
          mma_bf16(sa[nt * 2 + 1], ah, &blf[2]);
          mma_bf16(sa[nt * 2 + 1], al, &bhf[2]);
        }
      }

      // ---- causal mask ----
      if (kt * 64 + 63 > q0w) {
        int r0g = q0w + (lane >> 2);
#pragma unroll
        for (int t = 0; t < 8; t++) {
          int c0 = kt * 64 + t * 8 + ((lane & 3) << 1);
          if (c0     > r0g)     sa[t][0] = -1e30f;
          if (c0 + 1 > r0g)     sa[t][1] = -1e30f;
          if (c0     > r0g + 8) sa[t][2] = -1e30f;
          if (c0 + 1 > r0g + 8) sa[t][3] = -1e30f;
        }
      }

      // ---- online softmax (rows r, r+8) ----
      float mx0 = -INFINITY, mx1 = -INFINITY;
#pragma unroll
      for (int t = 0; t < 8; t++) {
        mx0 = fmaxf(mx0, fmaxf(sa[t][0], sa[t][1]));
        mx1 = fmaxf(mx1, fmaxf(sa[t][2], sa[t][3]));
      }
      mx0 = fmaxf(mx0, __shfl_xor_sync(0xffffffffu, mx0, 1));
      mx0 = fmaxf(mx0, __shfl_xor_sync(0xffffffffu, mx0, 2));
      mx1 = fmaxf(mx1, __shfl_xor_sync(0xffffffffu, mx1, 1));
      mx1 = fmaxf(mx1, __shfl_xor_sync(0xffffffffu, mx1, 2));
      float mn0 = fmaxf(m0, mx0), mn1 = fmaxf(m1, mx1);
      float f0 = __expf(m0 - mn0), f1 = __expf(m1 - mn1);
      m0 = mn0; m1 = mn1;
      float s0 = 0.f, s1 = 0.f;
#pragma unroll
      for (int t = 0; t < 8; t++) {
        sa[t][0] = __expf(sa[t][0] - mn0);
        sa[t][1] = __expf(sa[t][1] - mn0);
        sa[t][2] = __expf(sa[t][2] - mn1);
        sa[t][3] = __expf(sa[t][3] - mn1);
        s0 += sa[t][0] + sa[t][1];
        s1 += sa[t][2] + sa[t][3];
      }
      s0 += __shfl_xor_sync(0xffffffffu, s0, 1);
      s0 += __shfl_xor_sync(0xffffffffu, s0, 2);
      s1 += __shfl_xor_sync(0xffffffffu, s1, 1);
      s1 += __shfl_xor_sync(0xffffffffu, s1, 2);
      l0 = l0 * f0 + s0;
      l1 = l1 * f1 + s1;
#pragma unroll
      for (int g = 0; g < 16; g++) {
        oa[g][0] *= f0; oa[g][1] *= f0;
        oa[g][2] *= f1; oa[g][3] *= f1;
      }

      // ---- O += P @ V  (P in registers, split; V split) ----
#pragma unroll
      for (int kk2 = 0; kk2 < 4; kk2++) {
        uint32_t ahp[4], alp[4];
        split_pack(sa[2 * kk2][0],     sa[2 * kk2][1],     ahp[0], alp[0]);
        split_pack(sa[2 * kk2][2],     sa[2 * kk2][3],     ahp[1], alp[1]);
        split_pack(sa[2 * kk2 + 1][0], sa[2 * kk2 + 1][1], ahp[2], alp[2]);
        split_pack(sa[2 * kk2 + 1][2], sa[2 * kk2 + 1][3], ahp[3], alp[3]);
#pragma unroll
        for (int g7 = 0; g7 < 8; g7++) {
          uint32_t bvh[4], bvl[4];
          uint32_t vo = SWZ128((g7 * 16 + b_rw) * 128 + (uint32_t)kk2 * 32 + b_seg);
          ldsm_x4(bvh, sV + vo);
          ldsm_x4(bvl, sV + 16384 + vo);
          mma_bf16(oa[g7 * 2],     ahp, &bvh[0]);
          mma_bf16(oa[g7 * 2],     ahp, &bvl[0]);
          mma_bf16(oa[g7 * 2],     alp, &bvh[0]);
          mma_bf16(oa[g7 * 2 + 1], ahp, &bvh[2]);
          mma_bf16(oa[g7 * 2 + 1], ahp, &bvl[2]);
          mma_bf16(oa[g7 * 2 + 1], alp, &bvh[2]);
        }
      }
    }
    __syncthreads();
  }

  // ---- epilogue: normalize and store split-bf16 directly ----
  {
    float inv0 = 1.f / l0, inv1 = 1.f / l1;
    const size_t r0 = (size_t)(b * S_ + q0w + (lane >> 2)) * QD_;
    const size_t r1 = r0 + (size_t)8 * QD_;
    const int cb = h * HD_ + ((lane & 3) << 1);
#pragma unroll
    for (int g = 0; g < 16; g++) {
      uint32_t hi, lo;
      split_pack(oa[g][0] * inv0, oa[g][1] * inv0, hi, lo);
      *(uint32_t*)(Ohi_g + r0 + cb + g * 8) = hi;
      *(uint32_t*)(Olo_g + r0 + cb + g * 8) = lo;
      split_pack(oa[g][2] * inv1, oa[g][3] * inv1, hi, lo);
      *(uint32_t*)(Ohi_g + r1 + cb + g * 8) = hi;
      *(uint32_t*)(Olo_g + r1 + cb + g * 8) = lo;
    }
  }
}

// ---------------------------------------------------------------------------
extern "C" void kernel_launch(void* const* d_in, const int* in_sizes, int n_in,
                              void* d_out, int out_size) {
  const float* hs   = (const float*)d_in[0];
  const float* cosb = (const float*)d_in[1];
  const float* sinb = (const float*)d_in[2];
  const float* wq   = (const float*)d_in[3];
  const float* wk   = (const float*)d_in[4];
  const float* wv   = (const float*)d_in[5];
  const float* wo   = (const float*)d_in[6];
  float* out = (float*)d_out;

  float* qkv;
  cudaGetSymbolAddress((void**)&qkv, g_qkv);

  __nv_bfloat16 *hshi, *hslo, *athi, *atlo;
  __nv_bfloat16 *wqkvh, *wqkvl, *woh, *wol;
  __nv_bfloat16 *qhi, *qlo, *khi, *klo, *vthi, *vtlo;
  cudaGetSymbolAddress((void**)&hshi, g_hs_hi);
  cudaGetSymbolAddress((void**)&hslo, g_hs_lo);
  cudaGetSymbolAddress((void**)&athi, g_at_hi);
  cudaGetSymbolAddress((void**)&atlo, g_at_lo);
  cudaGetSymbolAddress((void**)&wqkvh, g_wqkvT_hi);
  cudaGetSymbolAddress((void**)&wqkvl, g_wqkvT_lo);
  cudaGetSymbolAddress((void**)&woh, g_woT_hi);
  cudaGetSymbolAddress((void**)&wol, g_woT_lo);
  cudaGetSymbolAddress((void**)&qhi, g_q_hi);
  cudaGetSymbolAddress((void**)&qlo, g_q_lo);
  cudaGetSymbolAddress((void**)&khi, g_k_hi);
  cudaGetSymbolAddress((void**)&klo, g_k_lo);
  cudaGetSymbolAddress((void**)&vthi, g_vt_hi);
  cudaGetSymbolAddress((void**)&vtlo, g_vt_lo);

  cudaFuncSetAttribute(wm_gemm_kernel,
                       cudaFuncAttributeMaxDynamicSharedMemorySize, GEMM_SMEM);
  cudaFuncSetAttribute(flash_hmma_kernel,
                       cudaFuncAttributeMaxDynamicSharedMemorySize, FLASH2_SMEM);

  // split hidden states; transpose+split weights (wq|wk|wv fused rows)
  split_kernel<<<(size_t)BS_ * H_ / 1024, 256>>>(hs, hshi, hslo);
  transpose_split_kernel<<<dim3(QD_ / 32, H_ / 32), dim3(32, 8)>>>(
      wq, wqkvh, wqkvl, H_, QD_);
  transpose_split_kernel<<<dim3(KD_ / 32, H_ / 32), dim3(32, 8)>>>(
      wk, wqkvh + (size_t)QD_ * H_, wqkvl + (size_t)QD_ * H_, H_, KD_);
  transpose_split_kernel<<<dim3(KD_ / 32, H_ / 32), dim3(32, 8)>>>(
      wv, wqkvh + (size_t)(QD_ + KD_) * H_, wqkvl + (size_t)(QD_ + KD_) * H_,
      H_, KD_);
  transpose_split_kernel<<<dim3(H_ / 32, QD_ / 32), dim3(32, 8)>>>(
      wo, woh, wol, QD_, H_);

  // fused QKV projection (warp MMA, 128x128 tiles)
  wm_gemm_kernel<<<dim3(QKVD_ / 128, BS_ / 128), 256, GEMM_SMEM>>>(
      hshi, hslo, wqkvh, wqkvl, qkv, BS_, QKVD_, H_);

  // RoPE + split (scale folded into Q); V transpose + split
  {
    int total = B_ * S_ * (NH_ + NKV_) * 64;
    rope_split_kernel<<<total / 256, 256>>>(qkv, cosb, sinb, qhi, qlo, khi, klo);
  }
  vt_split_kernel<<<dim3(S_ / 32, HD_ / 32, B_ * NKV_), dim3(32, 8)>>>(
      qkv, vthi, vtlo);

  // Causal GQA flash attention (HMMA split-bf16), writes split output
  flash_hmma_kernel<<<dim3(S_ / 128, NH_, B_), 256, FLASH2_SMEM>>>(
      qhi, qlo, khi, klo, vthi, vtlo, athi, atlo);

  // O projection
  wm_gemm_kernel<<<dim3(H_ / 128, BS_ / 128), 256, GEMM_SMEM>>>(
      athi, atlo, woh, wol, out, BS_, H_, H_);
}

// round 15
// speedup vs baseline: 1.3212x; 1.2513x over previous
#include <cuda_runtime.h>
#include <cuda_bf16.h>
#include <cuda_fp16.h>
#include <math.h>
#include <stdint.h>

// Problem constants
constexpr int B_   = 2;
constexpr int S_   = 2048;
constexpr int H_   = 4096;
constexpr int NH_  = 32;
constexpr int NKV_ = 8;
constexpr int HD_  = 128;
constexpr int BS_  = B_ * S_;        // 4096 rows
constexpr int QD_  = NH_ * HD_;      // 4096
constexpr int KD_  = NKV_ * HD_;     // 1024
constexpr int QKVD_ = QD_ + 2 * KD_; // 6144

// ---------------------------------------------------------------------------
// Scratch (device globals; no allocation allowed)
// ---------------------------------------------------------------------------
__device__ float g_qkv[(size_t)BS_ * QKVD_];   // fused QKV GEMM out (fp32)

// split-bf16 operands (QKV GEMM)
__device__ __nv_bfloat16 g_hs_hi[(size_t)BS_ * H_];
__device__ __nv_bfloat16 g_hs_lo[(size_t)BS_ * H_];
__device__ __nv_bfloat16 g_wqkvT_hi[(size_t)QKVD_ * H_];
__device__ __nv_bfloat16 g_wqkvT_lo[(size_t)QKVD_ * H_];

// fp16 operands (O projection, linear error path)
__device__ __half g_at_f16[(size_t)BS_ * QD_];
__device__ __half g_woT_f16[(size_t)H_ * QD_];

// split-bf16 operands (flash): rope'd Q (scaled) / K, transposed V
__device__ __nv_bfloat16 g_q_hi[(size_t)BS_ * QD_];
__device__ __nv_bfloat16 g_q_lo[(size_t)BS_ * QD_];
__device__ __nv_bfloat16 g_k_hi[(size_t)BS_ * KD_];
__device__ __nv_bfloat16 g_k_lo[(size_t)BS_ * KD_];
__device__ __nv_bfloat16 g_vt_hi[(size_t)B_ * NKV_ * HD_ * S_];
__device__ __nv_bfloat16 g_vt_lo[(size_t)B_ * NKV_ * HD_ * S_];

// ---------------------------------------------------------------------------
// PTX helpers (BASE target only — no sm_103a-suffixed instructions)
// ---------------------------------------------------------------------------
__device__ __forceinline__ uint32_t smem_u32(const void* p) {
  uint32_t a;
  asm("{ .reg .u64 t; cvta.to.shared.u64 t, %1; cvt.u32.u64 %0, t; }"
      : "=r"(a) : "l"(p));
  return a;
}
#define SWZ128(off) ((off) ^ (((off) >> 3) & 0x70))

__device__ __forceinline__ void cp_async16(uint32_t saddr, const void* gaddr) {
  asm volatile("cp.async.cg.shared.global [%0], [%1], 16;"
               :: "r"(saddr), "l"(gaddr));
}
#define CP_COMMIT() asm volatile("cp.async.commit_group;" ::: "memory")
#define CP_WAIT(n)  asm volatile("cp.async.wait_group %0;" :: "n"(n) : "memory")

__device__ __forceinline__ void ldsm_x4(uint32_t* r, uint32_t addr) {
  asm volatile("ldmatrix.sync.aligned.m8n8.x4.shared.b16 {%0,%1,%2,%3}, [%4];"
               : "=r"(r[0]), "=r"(r[1]), "=r"(r[2]), "=r"(r[3]) : "r"(addr));
}
__device__ __forceinline__ void mma_bf16(float* d, const uint32_t* a,
                                         const uint32_t* b) {
  asm volatile(
      "mma.sync.aligned.m16n8k16.row.col.f32.bf16.bf16.f32 "
      "{%0,%1,%2,%3}, {%4,%5,%6,%7}, {%8,%9}, {%0,%1,%2,%3};"
      : "+f"(d[0]), "+f"(d[1]), "+f"(d[2]), "+f"(d[3])
      : "r"(a[0]), "r"(a[1]), "r"(a[2]), "r"(a[3]), "r"(b[0]), "r"(b[1]));
}
__device__ __forceinline__ void mma_f16(float* d, const uint32_t* a,
                                        const uint32_t* b) {
  asm volatile(
      "mma.sync.aligned.m16n8k16.row.col.f32.f16.f16.f32 "
      "{%0,%1,%2,%3}, {%4,%5,%6,%7}, {%8,%9}, {%0,%1,%2,%3};"
      : "+f"(d[0]), "+f"(d[1]), "+f"(d[2]), "+f"(d[3])
      : "r"(a[0]), "r"(a[1]), "r"(a[2]), "r"(a[3]), "r"(b[0]), "r"(b[1]));
}
__device__ __forceinline__ uint32_t pack_bf16x2(float x, float y) {
  uint32_t r;  // low half = x, high half = y
  asm("cvt.rn.bf16x2.f32 %0, %1, %2;" : "=r"(r) : "f"(y), "f"(x));
  return r;
}
__device__ __forceinline__ void split_pack(float x, float y,
                                           uint32_t& hi, uint32_t& lo) {
  uint32_t h = pack_bf16x2(x, y);
  float hx = __uint_as_float(h << 16);
  float hy = __uint_as_float(h & 0xFFFF0000u);
  lo = pack_bf16x2(x - hx, y - hy);
  hi = h;
}

// ---------------------------------------------------------------------------
// split conversions
// ---------------------------------------------------------------------------
__global__ void split_kernel(const float* __restrict__ X,
                             __nv_bfloat16* __restrict__ Hi,
                             __nv_bfloat16* __restrict__ Lo) {
  size_t i = ((size_t)blockIdx.x * blockDim.x + threadIdx.x) * 4;
  float4 v = *(const float4*)(X + i);
  __nv_bfloat162 h01 = __floats2bfloat162_rn(v.x, v.y);
  __nv_bfloat162 h23 = __floats2bfloat162_rn(v.z, v.w);
  float lx = v.x - __bfloat162float(h01.x);
  float ly = v.y - __bfloat162float(h01.y);
  float lz = v.z - __bfloat162float(h23.x);
  float lw = v.w - __bfloat162float(h23.y);
  *(__nv_bfloat162*)(Hi + i)     = h01;
  *(__nv_bfloat162*)(Hi + i + 2) = h23;
  *(__nv_bfloat162*)(Lo + i)     = __floats2bfloat162_rn(lx, ly);
  *(__nv_bfloat162*)(Lo + i + 2) = __floats2bfloat162_rn(lz, lw);
}

// W[K,N] fp32 -> T[N,K] bf16 hi/lo (transpose + split)
__global__ void transpose_split_kernel(const float* __restrict__ W,
                                       __nv_bfloat16* __restrict__ Thi,
                                       __nv_bfloat16* __restrict__ Tlo,
                                       int K, int N) {
  __shared__ float tile[32][33];
  int n0 = blockIdx.x * 32, k0 = blockIdx.y * 32;
  int tx = threadIdx.x, ty = threadIdx.y;  // 32 x 8
#pragma unroll
  for (int i = 0; i < 32; i += 8)
    tile[ty + i][tx] = W[(size_t)(k0 + ty + i) * N + n0 + tx];
  __syncthreads();
#pragma unroll
  for (int i = 0; i < 32; i += 8) {
    float v = tile[tx][ty + i];
    __nv_bfloat16 h = __float2bfloat16_rn(v);
    __nv_bfloat16 l = __float2bfloat16_rn(v - __bfloat162float(h));
    size_t o = (size_t)(n0 + ty + i) * K + k0 + tx;
    Thi[o] = h;
    Tlo[o] = l;
  }
}

// W[K,N] fp32 -> T[N,K] fp16 (transpose, single precision level)
__global__ void transpose_f16_kernel(const float* __restrict__ W,
                                     __half* __restrict__ T,
                                     int K, int N) {
  __shared__ float tile[32][33];
  int n0 = blockIdx.x * 32, k0 = blockIdx.y * 32;
  int tx = threadIdx.x, ty = threadIdx.y;  // 32 x 8
#pragma unroll
  for (int i = 0; i < 32; i += 8)
    tile[ty + i][tx] = W[(size_t)(k0 + ty + i) * N + n0 + tx];
  __syncthreads();
#pragma unroll
  for (int i = 0; i < 32; i += 8)
    T[(size_t)(n0 + ty + i) * K + k0 + tx] = __float2half_rn(tile[tx][ty + i]);
}

// ---------------------------------------------------------------------------
// Warp-MMA split-bf16 GEMM: C[M,N] = A[M,K] @ T[N,K]^T   (R10/R14 config)
// 128x128 tile/CTA, 8 warps (64x32 each), K chunks of 64, double-buffered
// cp.async. 3 products per chunk: Ahi*Bhi + Ahi*Blo + Alo*Bhi.
// ---------------------------------------------------------------------------
constexpr int TILE_B    = 128 * 128;
constexpr int STAGE_B   = 4 * TILE_B;
constexpr int GEMM_SMEM = 2 * STAGE_B + 1024;

__global__ __launch_bounds__(256) void wm_gemm_kernel(
    const __nv_bfloat16* __restrict__ Ahi, const __nv_bfloat16* __restrict__ Alo,
    const __nv_bfloat16* __restrict__ Bhi, const __nv_bfloat16* __restrict__ Blo,
    float* __restrict__ C, int M, int N, int K) {
  extern __shared__ char dsm[];
  const uint32_t sbase = (smem_u32(dsm) + 1023u) & ~1023u;

  const int tid = threadIdx.x;
  const int wid = tid >> 5, lane = tid & 31;
  const int m0 = blockIdx.y * 128, n0 = blockIdx.x * 128;
  const int m0w = (wid & 1) * 64;
  const int n0w = (wid >> 1) * 32;

  const int seg = tid & 7;
  const int rb  = tid >> 3;
  const size_t Kb = (size_t)K * 2;
  const char* pAhi = (const char*)Ahi + (size_t)(m0 + rb) * Kb + seg * 16;
  const char* pAlo = (const char*)Alo + (size_t)(m0 + rb) * Kb + seg * 16;
  const char* pBhi = (const char*)Bhi + (size_t)(n0 + rb) * Kb + seg * 16;
  const char* pBlo = (const char*)Blo + (size_t)(n0 + rb) * Kb + seg * 16;

  const int rr = lane & 7;
  const int jj = lane >> 3;
  const uint32_t a_row = (uint32_t)(m0w + ((jj & 1) << 3) + rr);
  const uint32_t a_seg = (uint32_t)((jj >> 1) << 4);
  const uint32_t b_row = (uint32_t)(n0w + ((jj >> 1) << 3) + rr);
  const uint32_t b_seg = (uint32_t)((jj & 1) << 4);

  float acc[4][4][4];
#pragma unroll
  for (int i = 0; i < 4; i++)
#pragma unroll
    for (int j = 0; j < 4; j++)
#pragma unroll
      for (int t = 0; t < 4; t++) acc[i][j][t] = 0.f;

  const int NC = K / 64;

#pragma unroll
  for (int i = 0; i < 4; i++) {
    uint32_t so = SWZ128((uint32_t)((rb + 32 * i) * 128 + seg * 16));
    size_t go = (size_t)(32 * i) * Kb;
    cp_async16(sbase + so,              pAhi + go);
    cp_async16(sbase + TILE_B + so,     pAlo + go);
    cp_async16(sbase + 2 * TILE_B + so, pBhi + go);
    cp_async16(sbase + 3 * TILE_B + so, pBlo + go);
  }
  CP_COMMIT();

  for (int c = 0; c < NC; c++) {
    if (c + 1 < NC) {
      const uint32_t sb = sbase + (uint32_t)((c + 1) & 1) * STAGE_B;
      const size_t kb = (size_t)(c + 1) * 128;
#pragma unroll
      for (int i = 0; i < 4; i++) {
        uint32_t so = SWZ128((uint32_t)((rb + 32 * i) * 128 + seg * 16));
        size_t go = (size_t)(32 * i) * Kb + kb;
        cp_async16(sb + so,              pAhi + go);
        cp_async16(sb + TILE_B + so,     pAlo + go);
        cp_async16(sb + 2 * TILE_B + so, pBhi + go);
        cp_async16(sb + 3 * TILE_B + so, pBlo + go);
      }
      CP_COMMIT();
      CP_WAIT(1);
    } else {
      CP_WAIT(0);
    }
    __syncthreads();

    const uint32_t sb   = sbase + (uint32_t)(c & 1) * STAGE_B;
    const uint32_t sAhi = sb;
    const uint32_t sAlo = sb + TILE_B;
    const uint32_t sBhi = sb + 2 * TILE_B;
    const uint32_t sBlo = sb + 3 * TILE_B;

#pragma unroll
    for (int kk = 0; kk < 4; kk++) {
      uint32_t ah[4][4], al[4][4], bh[2][4], bl[2][4];
      const uint32_t kbyte = (uint32_t)(kk * 32);
#pragma unroll
      for (int mt = 0; mt < 4; mt++) {
        uint32_t off = SWZ128((a_row + mt * 16) * 128 + kbyte + a_seg);
        ldsm_x4(ah[mt], sAhi + off);
        ldsm_x4(al[mt], sAlo + off);
      }
#pragma unroll
      for (int nt = 0; nt < 2; nt++) {
        uint32_t off = SWZ128((b_row + nt * 16) * 128 + kbyte + b_seg);
        ldsm_x4(bh[nt], sBhi + off);
        ldsm_x4(bl[nt], sBlo + off);
      }
#pragma unroll
      for (int mt = 0; mt < 4; mt++)
#pragma unroll
        for (int nt8 = 0; nt8 < 4; nt8++) {
          const int n16 = nt8 >> 1, hf = (nt8 & 1) * 2;
          mma_bf16(acc[mt][nt8], ah[mt], &bh[n16][hf]);
          mma_bf16(acc[mt][nt8], ah[mt], &bl[n16][hf]);
          mma_bf16(acc[mt][nt8], al[mt], &bh[n16][hf]);
        }
    }
    __syncthreads();
  }

  const int grp = lane >> 2;
  const int cq  = (lane & 3) * 2;
#pragma unroll
  for (int mt = 0; mt < 4; mt++) {
    const int row = m0 + m0w + mt * 16 + grp;
#pragma unroll
    for (int nt8 = 0; nt8 < 4; nt8++) {
      const int col = n0 + n0w + nt8 * 8 + cq;
      float* c0 = C + (size_t)row * N + col;
      float* c1 = C + (size_t)(row + 8) * N + col;
      *(float2*)c0 = make_float2(acc[mt][nt8][0], acc[mt][nt8][1]);
      *(float2*)c1 = make_float2(acc[mt][nt8][2], acc[mt][nt8][3]);
    }
  }
}

// ---------------------------------------------------------------------------
// Warp-MMA plain-fp16 GEMM (O projection): C[M,N] = A[M,K] @ T[N,K]^T
// Same geometry as split kernel; 1 product, 2 tiles/stage (32 KB), 2 stages.
// ---------------------------------------------------------------------------
constexpr int F16_STAGE_B = 2 * TILE_B;          // Af16 + Bf16, 32 KB
constexpr int F16_SMEM    = 2 * F16_STAGE_B + 1024;

__global__ __launch_bounds__(256) void wm_gemm_f16_kernel(
    const __half* __restrict__ A, const __half* __restrict__ Bw,
    float* __restrict__ C, int M, int N, int K) {
  extern __shared__ char dsm[];
  const uint32_t sbase = (smem_u32(dsm) + 1023u) & ~1023u;

  const int tid = threadIdx.x;
  const int wid = tid >> 5, lane = tid & 31;
  const int m0 = blockIdx.y * 128, n0 = blockIdx.x * 128;
  const int m0w = (wid & 1) * 64;
  const int n0w = (wid >> 1) * 32;

  const int seg = tid & 7;
  const int rb  = tid >> 3;
  const size_t Kb = (size_t)K * 2;
  const char* pA = (const char*)A  + (size_t)(m0 + rb) * Kb + seg * 16;
  const char* pB = (const char*)Bw + (size_t)(n0 + rb) * Kb + seg * 16;

  const int rr = lane & 7;
  const int jj = lane >> 3;
  const uint32_t a_row = (uint32_t)(m0w + ((jj & 1) << 3) + rr);
  const uint32_t a_seg = (uint32_t)((jj >> 1) << 4);
  const uint32_t b_row = (uint32_t)(n0w + ((jj >> 1) << 3) + rr);
  const uint32_t b_seg = (uint32_t)((jj & 1) << 4);

  float acc[4][4][4];
#pragma unroll
  for (int i = 0; i < 4; i++)
#pragma unroll
    for (int j = 0; j < 4; j++)
#pragma unroll
      for (int t = 0; t < 4; t++) acc[i][j][t] = 0.f;

  const int NC = K / 64;

#pragma unroll
  for (int i = 0; i < 4; i++) {
    uint32_t so = SWZ128((uint32_t)((rb + 32 * i) * 128 + seg * 16));
    size_t go = (size_t)(32 * i) * Kb;
    cp_async16(sbase + so,          pA + go);
    cp_async16(sbase + TILE_B + so, pB + go);
  }
  CP_COMMIT();

  for (int c = 0; c < NC; c++) {
    if (c + 1 < NC) {
      const uint32_t sb = sbase + (uint32_t)((c + 1) & 1) * F16_STAGE_B;
      const size_t kb = (size_t)(c + 1) * 128;
#pragma unroll
      for (int i = 0; i < 4; i++) {
        uint32_t so = SWZ128((uint32_t)((rb + 32 * i) * 128 + seg * 16));
        size_t go = (size_t)(32 * i) * Kb + kb;
        cp_async16(sb + so,          pA + go);
        cp_async16(sb + TILE_B + so, pB + go);
      }
      CP_COMMIT();
      CP_WAIT(1);
    } else {
      CP_WAIT(0);
    }
    __syncthreads();

    const uint32_t sb = sbase + (uint32_t)(c & 1) * F16_STAGE_B;
    const uint32_t sA = sb;
    const uint32_t sB = sb + TILE_B;

#pragma unroll
    for (int kk = 0; kk < 4; kk++) {
      uint32_t af[4][4], bf[2][4];
      const uint32_t kbyte = (uint32_t)(kk * 32);
#pragma unroll
      for (int mt = 0; mt < 4; mt++) {
        uint32_t off = SWZ128((a_row + mt * 16) * 128 + kbyte + a_seg);
        ldsm_x4(af[mt], sA + off);
      }
#pragma unroll
      for (int nt = 0; nt < 2; nt++) {
        uint32_t off = SWZ128((b_row + nt * 16) * 128 + kbyte + b_seg);
        ldsm_x4(bf[nt], sB + off);
      }
#pragma unroll
      for (int mt = 0; mt < 4; mt++)
#pragma unroll
        for (int nt8 = 0; nt8 < 4; nt8++) {
          const int n16 = nt8 >> 1, hf = (nt8 & 1) * 2;
          mma_f16(acc[mt][nt8], af[mt], &bf[n16][hf]);
        }
    }
    __syncthreads();
  }

  const int grp = lane >> 2;
  const int cq  = (lane & 3) * 2;
#pragma unroll
  for (int mt = 0; mt < 4; mt++) {
    const int row = m0 + m0w + mt * 16 + grp;
#pragma unroll
    for (int nt8 = 0; nt8 < 4; nt8++) {
      const int col = n0 + n0w + nt8 * 8 + cq;
      float* c0 = C + (size_t)row * N + col;
      float* c1 = C + (size_t)(row + 8) * N + col;
      *(float2*)c0 = make_float2(acc[mt][nt8][0], acc[mt][nt8][1]);
      *(float2*)c1 = make_float2(acc[mt][nt8][2], acc[mt][nt8][3]);
    }
  }
}

// ---------------------------------------------------------------------------
// RoPE + split to bf16 hi/lo from fused qkv buffer. Q gets softmax scale.
// ---------------------------------------------------------------------------
__global__ void rope_split_kernel(const float* __restrict__ qkv,
                                  const float* __restrict__ cosb,
                                  const float* __restrict__ sinb,
                                  __nv_bfloat16* __restrict__ qhi,
                                  __nv_bfloat16* __restrict__ qlo,
                                  __nv_bfloat16* __restrict__ khi,
                                  __nv_bfloat16* __restrict__ klo) {
  int gid = blockIdx.x * blockDim.x + threadIdx.x;
  int d = gid & 63;
  int t = gid >> 6;
  int hh = t % (NH_ + NKV_);
  int bs = t / (NH_ + NKV_);
  float c  = cosb[bs * HD_ + d];
  float sn = sinb[bs * HD_ + d];
  if (hh < NH_) {
    size_t src = (size_t)bs * QKVD_ + hh * HD_ + d;
    size_t off = (size_t)bs * QD_ + hh * HD_ + d;
    const float scale = 0.08838834764831845f;  // 1/sqrt(128)
    float x1 = qkv[src], x2 = qkv[src + 64];
    float y1 = (x1 * c - x2 * sn) * scale;
    float y2 = (x2 * c + x1 * sn) * scale;
    __nv_bfloat16 h1 = __float2bfloat16_rn(y1);
    __nv_bfloat16 h2 = __float2bfloat16_rn(y2);
    qhi[off]      = h1;
    qlo[off]      = __float2bfloat16_rn(y1 - __bfloat162float(h1));
    qhi[off + 64] = h2;
    qlo[off + 64] = __float2bfloat16_rn(y2 - __bfloat162float(h2));
  } else {
    int kvh = hh - NH_;
    size_t src = (size_t)bs * QKVD_ + QD_ + kvh * HD_ + d;
    size_t off = (size_t)bs * KD_ + kvh * HD_ + d;
    float x1 = qkv[src], x2 = qkv[src + 64];
    float y1 = x1 * c - x2 * sn;
    float y2 = x2 * c + x1 * sn;
    __nv_bfloat16 h1 = __float2bfloat16_rn(y1);
    __nv_bfloat16 h2 = __float2bfloat16_rn(y2);
    khi[off]      = h1;
    klo[off]      = __float2bfloat16_rn(y1 - __bfloat162float(h1));
    khi[off + 64] = h2;
    klo[off + 64] = __float2bfloat16_rn(y2 - __bfloat162float(h2));
  }
}

// V slice of qkv -> Vt [(b*NKV+kvh)*128+d][s] bf16 hi/lo
__global__ void vt_split_kernel(const float* __restrict__ qkv,
                                __nv_bfloat16* __restrict__ vthi,
                                __nv_bfloat16* __restrict__ vtlo) {
  __shared__ float tl[32][33];
  int s0 = blockIdx.x * 32, d0 = blockIdx.y * 32, bh = blockIdx.z;
  int b = bh >> 3, kvh = bh & 7;
  int tx = threadIdx.x, ty = threadIdx.y;  // 32 x 8
#pragma unroll
  for (int i = 0; i < 32; i += 8)
    tl[ty + i][tx] = qkv[(size_t)(b * S_ + s0 + ty + i) * QKVD_ +
                         QD_ + KD_ + kvh * HD_ + d0 + tx];
  __syncthreads();
#pragma unroll
  for (int i = 0; i < 32; i += 8) {
    float val = tl[tx][ty + i];  // s = s0+tx, d = d0+ty+i
    __nv_bfloat16 h = __float2bfloat16_rn(val);
    __nv_bfloat16 l = __float2bfloat16_rn(val - __bfloat162float(h));
    size_t o = ((size_t)bh * HD_ + d0 + ty + i) * S_ + s0 + tx;
    vthi[o] = h;
    vtlo[o] = l;
  }
}

// ---------------------------------------------------------------------------
// Flash attention, HMMA split-bf16. Writes fp16 output directly (O-proj A).
// BQ=128 (8 warps x m16), BKT=64, double-buffered K/V, Q resident.
// ---------------------------------------------------------------------------
constexpr int FLASH2_SMEM = 196608;

__global__ __launch_bounds__(256, 1) void flash_hmma_kernel(
    const __nv_bfloat16* __restrict__ Qhi_g, const __nv_bfloat16* __restrict__ Qlo_g,
    const __nv_bfloat16* __restrict__ Khi_g, const __nv_bfloat16* __restrict__ Klo_g,
    const __nv_bfloat16* __restrict__ Vthi_g, const __nv_bfloat16* __restrict__ Vtlo_g,
    __half* __restrict__ Of16_g) {
  extern __shared__ char sm[];
  const uint32_t sb = smem_u32(sm);
  const int qt = blockIdx.x, h = blockIdx.y, b = blockIdx.z;
  const int kvh = h >> 2;                 // n_rep = 4
  const int tid = threadIdx.x, wid = tid >> 5, lane = tid & 31;
  const int q0 = qt * 128;
  const int q0w = q0 + wid * 16;

  const uint32_t sQhi = sb;               // 2 chunks of 16KB (d halves)
  const uint32_t sQlo = sb + 32768;
  const uint32_t sKb  = sb + 65536;       // + buf*32768; hi chunks 0/8K, lo +16K
  const uint32_t sVb  = sb + 131072;      // + buf*32768; hi 0, lo +16K

  // ---- Q tile load (hi+lo) ----
  {
    const int seg = tid & 15, r0 = tid >> 4;
    const size_t qoff = ((size_t)(b * S_ + q0) * QD_ + h * HD_) * 2;
    const char* ph = (const char*)Qhi_g + qoff;
    const char* pl = (const char*)Qlo_g + qoff;
#pragma unroll
    for (int i = 0; i < 8; i++) {
      int r = r0 + i * 16;
      uint32_t off = ((seg >> 3) * 16384) +
                     SWZ128((uint32_t)(r * 128 + (seg & 7) * 16));
      size_t g = (size_t)r * (QD_ * 2) + seg * 16;
      cp_async16(sQhi + off, ph + g);
      cp_async16(sQlo + off, pl + g);
    }
  }
  CP_COMMIT();

  const int nkt = 2 * qt + 2;

  auto load_kv = [&](int kt, int buf) {
    const uint32_t sK = sKb + (uint32_t)buf * 32768;
    const uint32_t sV = sVb + (uint32_t)buf * 32768;
    {
      const int seg = tid & 15, r0 = tid >> 4;
      const size_t koff = ((size_t)(b * S_ + kt * 64) * KD_ + kvh * HD_) * 2;
      const char* ph = (const char*)Khi_g + koff;
      const char* pl = (const char*)Klo_g + koff;
#pragma unroll
      for (int i = 0; i < 4; i++) {
        int r = r0 + i * 16;
        uint32_t off = ((seg >> 3) * 8192) +
                       SWZ128((uint32_t)(r * 128 + (seg & 7) * 16));
        size_t g = (size_t)r * (KD_ * 2) + seg * 16;
        cp_async16(sK + off,         ph + g);
        cp_async16(sK + 16384 + off, pl + g);
      }
    }
    {
      const int seg = tid & 7, d0 = tid >> 3;
      const size_t voff = ((size_t)(b * NKV_ + kvh) * HD_ * S_ + (size_t)kt * 64) * 2;
      const char* ph = (const char*)Vthi_g + voff;
      const char* pl = (const char*)Vtlo_g + voff;
#pragma unroll
      for (int i = 0; i < 4; i++) {
        int d = d0 + i * 32;
        uint32_t off = SWZ128((uint32_t)(d * 128 + seg * 16));
        size_t g = (size_t)d * (S_ * 2) + seg * 16;
        cp_async16(sV + off,         ph + g);
        cp_async16(sV + 16384 + off, pl + g);
      }
    }
    CP_COMMIT();
  };

  load_kv(0, 0);

  // fragment addressing
  const int rr = lane & 7, jj = lane >> 3;
  const uint32_t a_row = (uint32_t)(wid * 16 + ((jj & 1) << 3) + rr);
  const uint32_t a_seg = (uint32_t)((jj >> 1) << 4);
  const uint32_t b_rw  = (uint32_t)(((jj >> 1) << 3) + rr);
  const uint32_t b_seg = (uint32_t)((jj & 1) << 4);

  float oa[16][4];
#pragma unroll
  for (int g = 0; g < 16; g++)
#pragma unroll
    for (int t = 0; t < 4; t++) oa[g][t] = 0.f;
  float m0 = -INFINITY, m1 = -INFINITY, l0 = 0.f, l1 = 0.f;

  for (int kt = 0; kt < nkt; kt++) {
    const int buf = kt & 1;
    if (kt + 1 < nkt) {
      load_kv(kt + 1, buf ^ 1);
      CP_WAIT(1);
    } else {
      CP_WAIT(0);
    }
    __syncthreads();

    if (kt * 64 <= q0w + 15) {  // tile intersects this warp's rows
      const uint32_t sK = sKb + (uint32_t)buf * 32768;
      const uint32_t sV = sVb + (uint32_t)buf * 32768;

      // ---- S = Q @ K^T (split-bf16, 3 products) ----
      float sa[8][4];
#pragma unroll
      for (int t = 0; t < 8; t++)
#pragma unroll
        for (int e = 0; e < 4; e++) sa[t][e] = 0.f;

#pragma unroll
      for (int kk = 0; kk < 8; kk++) {
        uint32_t ah[4], al[4];
        uint32_t qo = ((uint32_t)(kk >> 2) * 16384) +
                      SWZ128(a_row * 128 + (uint32_t)(kk & 3) * 32 + a_seg);
        ldsm_x4(ah, sQhi + qo);
        ldsm_x4(al, sQlo + qo);
#pragma unroll
        for (int nt = 0; nt < 4; nt++) {
          uint32_t bhf[4], blf[4];
          uint32_t ko = ((uint32_t)(kk >> 2) * 8192) +
                        SWZ128((b_rw + nt * 16) * 128 + (uint32_t)(kk & 3) * 32 + b_seg);
          ldsm_x4(bhf, sK + ko);
          ldsm_x4(blf, sK + 16384 + ko);
          mma_bf16(sa[nt * 2],     ah, &bhf[0]);
          mma_bf16(sa[nt * 2],     ah, &blf[0]);
          mma_bf16(sa[nt * 2],     al, &bhf[0]);
          mma_bf16(sa[nt * 2 + 1], ah, &bhf[2]);
          mma_bf16(sa[nt * 2 + 1], ah, &blf[2]);
          mma_bf16(sa[nt * 2 + 1], al, &bhf[2]);
        }
      }

      // ---- causal mask ----
      if (kt * 64 + 63 > q0w) {
        int r0g = q0w + (lane >> 2);
#pragma unroll
        for (int t = 0; t < 8; t++) {
          int c0 = kt * 64 + t * 8 + ((lane & 3) << 1);
          if (c0     > r0g)     sa[t][0] = -1e30f;
          if (c0 + 1 > r0g)     sa[t][1] = -1e30f;
          if (c0     > r0g + 8) sa[t][2] = -1e30f;
          if (c0 + 1 > r0g + 8) sa[t][3] = -1e30f;
        }
      }

      // ---- online softmax (rows r, r+8) ----
      float mx0 = -INFINITY, mx1 = -INFINITY;
#pragma unroll
      for (int t = 0; t < 8; t++) {
        mx0 = fmaxf(mx0, fmaxf(sa[t][0], sa[t][1]));
        mx1 = fmaxf(mx1, fmaxf(sa[t][2], sa[t][3]));
      }
      mx0 = fmaxf(mx0, __shfl_xor_sync(0xffffffffu, mx0, 1));
      mx0 = fmaxf(mx0, __shfl_xor_sync(0xffffffffu, mx0, 2));
      mx1 = fmaxf(mx1, __shfl_xor_sync(0xffffffffu, mx1, 1));
      mx1 = fmaxf(mx1, __shfl_xor_sync(0xffffffffu, mx1, 2));
      float mn0 = fmaxf(m0, mx0), mn1 = fmaxf(m1, mx1);
      float f0 = __expf(m0 - mn0), f1 = __expf(m1 - mn1);
      m0 = mn0; m1 = mn1;
      float s0 = 0.f, s1 = 0.f;
#pragma unroll
      for (int t = 0; t < 8; t++) {
        sa[t][0] = __expf(sa[t][0] - mn0);
        sa[t][1] = __expf(sa[t][1] - mn0);
        sa[t][2] = __expf(sa[t][2] - mn1);
        sa[t][3] = __expf(sa[t][3] - mn1);
        s0 += sa[t][0] + sa[t][1];
        s1 += sa[t][2] + sa[t][3];
      }
      s0 += __shfl_xor_sync(0xffffffffu, s0, 1);
      s0 += __shfl_xor_sync(0xffffffffu, s0, 2);
      s1 += __shfl_xor_sync(0xffffffffu, s1, 1);
      s1 += __shfl_xor_sync(0xffffffffu, s1, 2);
      l0 = l0 * f0 + s0;
      l1 = l1 * f1 + s1;
#pragma unroll
      for (int g = 0; g < 16; g++) {
        oa[g][0] *= f0; oa[g][1] *= f0;
        oa[g][2] *= f1; oa[g][3] *= f1;
      }

      // ---- O += P @ V  (P in registers, split; V split) ----
#pragma unroll
      for (int kk2 = 0; kk2 < 4; kk2++) {
        uint32_t ahp[4], alp[4];
        split_pack(sa[2 * kk2][0],     sa[2 * kk2][1],     ahp[0], alp[0]);
        split_pack(sa[2 * kk2][2],     sa[2 * kk2][3],     ahp[1], alp[1]);
        split_pack(sa[2 * kk2 + 1][0], sa[2 * kk2 + 1][1], ahp[2], alp[2]);
        split_pack(sa[2 * kk2 + 1][2], sa[2 * kk2 + 1][3], ahp[3], alp[3]);
#pragma unroll
        for (int g7 = 0; g7 < 8; g7++) {
          uint32_t bvh[4], bvl[4];
          uint32_t vo = SWZ128((g7 * 16 + b_rw) * 128 + (uint32_t)kk2 * 32 + b_seg);
          ldsm_x4(bvh, sV + vo);
          ldsm_x4(bvl, sV + 16384 + vo);
          mma_bf16(oa[g7 * 2],     ahp, &bvh[0]);
          mma_bf16(oa[g7 * 2],     ahp, &bvl[0]);
          mma_bf16(oa[g7 * 2],     alp, &bvh[0]);
          mma_bf16(oa[g7 * 2 + 1], ahp, &bvh[2]);
          mma_bf16(oa[g7 * 2 + 1], ahp, &bvl[2]);
          mma_bf16(oa[g7 * 2 + 1], alp, &bvh[2]);
        }
      }
    }
    __syncthreads();
  }

  // ---- epilogue: normalize and store fp16 directly ----
  {
    float inv0 = 1.f / l0, inv1 = 1.f / l1;
    const size_t r0 = (size_t)(b * S_ + q0w + (lane >> 2)) * QD_;
    const size_t r1 = r0 + (size_t)8 * QD_;
    const int cb = h * HD_ + ((lane & 3) << 1);
#pragma unroll
    for (int g = 0; g < 16; g++) {
      __half2 p0 = __floats2half2_rn(oa[g][0] * inv0, oa[g][1] * inv0);
      __half2 p1 = __floats2half2_rn(oa[g][2] * inv1, oa[g][3] * inv1);
      *(__half2*)(Of16_g + r0 + cb + g * 8) = p0;
      *(__half2*)(Of16_g + r1 + cb + g * 8) = p1;
    }
  }
}

// ---------------------------------------------------------------------------
extern "C" void kernel_launch(void* const* d_in, const int* in_sizes, int n_in,
                              void* d_out, int out_size) {
  const float* hs   = (const float*)d_in[0];
  const float* cosb = (const float*)d_in[1];
  const float* sinb = (const float*)d_in[2];
  const float* wq   = (const float*)d_in[3];
  const float* wk   = (const float*)d_in[4];
  const float* wv   = (const float*)d_in[5];
  const float* wo   = (const float*)d_in[6];
  float* out = (float*)d_out;

  float* qkv;
  cudaGetSymbolAddress((void**)&qkv, g_qkv);

  __nv_bfloat16 *hshi, *hslo, *wqkvh, *wqkvl;
  __nv_bfloat16 *qhi, *qlo, *khi, *klo, *vthi, *vtlo;
  __half *atf, *wof;
  cudaGetSymbolAddress((void**)&hshi, g_hs_hi);
  cudaGetSymbolAddress((void**)&hslo, g_hs_lo);
  cudaGetSymbolAddress((void**)&wqkvh, g_wqkvT_hi);
  cudaGetSymbolAddress((void**)&wqkvl, g_wqkvT_lo);
  cudaGetSymbolAddress((void**)&atf, g_at_f16);
  cudaGetSymbolAddress((void**)&wof, g_woT_f16);
  cudaGetSymbolAddress((void**)&qhi, g_q_hi);
  cudaGetSymbolAddress((void**)&qlo, g_q_lo);
  cudaGetSymbolAddress((void**)&khi, g_k_hi);
  cudaGetSymbolAddress((void**)&klo, g_k_lo);
  cudaGetSymbolAddress((void**)&vthi, g_vt_hi);
  cudaGetSymbolAddress((void**)&vtlo, g_vt_lo);

  cudaFuncSetAttribute(wm_gemm_kernel,
                       cudaFuncAttributeMaxDynamicSharedMemorySize, GEMM_SMEM);
  cudaFuncSetAttribute(wm_gemm_f16_kernel,
                       cudaFuncAttributeMaxDynamicSharedMemorySize, F16_SMEM);
  cudaFuncSetAttribute(flash_hmma_kernel,
                       cudaFuncAttributeMaxDynamicSharedMemorySize, FLASH2_SMEM);

  // split hidden states; transpose+split weights (wq|wk|wv fused rows)
  split_kernel<<<(size_t)BS_ * H_ / 1024, 256>>>(hs, hshi, hslo);
  transpose_split_kernel<<<dim3(QD_ / 32, H_ / 32), dim3(32, 8)>>>(
      wq, wqkvh, wqkvl, H_, QD_);
  transpose_split_kernel<<<dim3(KD_ / 32, H_ / 32), dim3(32, 8)>>>(
      wk, wqkvh + (size_t)QD_ * H_, wqkvl + (size_t)QD_ * H_, H_, KD_);
  transpose_split_kernel<<<dim3(KD_ / 32, H_ / 32), dim3(32, 8)>>>(
      wv, wqkvh + (size_t)(QD_ + KD_) * H_, wqkvl + (size_t)(QD_ + KD_) * H_,
      H_, KD_);
  transpose_f16_kernel<<<dim3(H_ / 32, QD_ / 32), dim3(32, 8)>>>(
      wo, wof, QD_, H_);

  // fused QKV projection (warp MMA, split-bf16, 128x128 tiles)
  wm_gemm_kernel<<<dim3(QKVD_ / 128, BS_ / 128), 256, GEMM_SMEM>>>(
      hshi, hslo, wqkvh, wqkvl, qkv, BS_, QKVD_, H_);

  // RoPE + split (scale folded into Q); V transpose + split
  {
    int total = B_ * S_ * (NH_ + NKV_) * 64;
    rope_split_kernel<<<total / 256, 256>>>(qkv, cosb, sinb, qhi, qlo, khi, klo);
  }
  vt_split_kernel<<<dim3(S_ / 32, HD_ / 32, B_ * NKV_), dim3(32, 8)>>>(
      qkv, vthi, vtlo);

  // Causal GQA flash attention (HMMA split-bf16), writes fp16 output
  flash_hmma_kernel<<<dim3(S_ / 128, NH_, B_), 256, FLASH2_SMEM>>>(
      qhi, qlo, khi, klo, vthi, vtlo, atf);

  // O projection (plain fp16, 1 product)
  wm_gemm_f16_kernel<<<dim3(H_ / 128, BS_ / 128), 256, F16_SMEM>>>(
      atf, wof, out, BS_, H_, QD_);
}

// round 16
// speedup vs baseline: 1.5235x; 1.1532x over previous
#include <cuda_runtime.h>
#include <cuda_bf16.h>
#include <cuda_fp16.h>
#include <math.h>
#include <stdint.h>

// Problem constants
constexpr int B_   = 2;
constexpr int S_   = 2048;
constexpr int H_   = 4096;
constexpr int NH_  = 32;
constexpr int NKV_ = 8;
constexpr int HD_  = 128;
constexpr int BS_  = B_ * S_;        // 4096 rows
constexpr int QD_  = NH_ * HD_;      // 4096
constexpr int KD_  = NKV_ * HD_;     // 1024
constexpr int QKD_ = QD_ + KD_;      // 5120 (fused Q|K GEMM width)

// ---------------------------------------------------------------------------
// Scratch (device globals; no allocation allowed)
// ---------------------------------------------------------------------------
__device__ float g_qk[(size_t)BS_ * QKD_];   // fused Q|K GEMM out (fp32)
__device__ float g_v[(size_t)BS_ * KD_];     // V GEMM out (fp32)

// split-bf16 operands (QK GEMM — softmax-amplified path)
__device__ __nv_bfloat16 g_hs_hi[(size_t)BS_ * H_];
__device__ __nv_bfloat16 g_hs_lo[(size_t)BS_ * H_];
__device__ __nv_bfloat16 g_wqkT_hi[(size_t)QKD_ * H_];
__device__ __nv_bfloat16 g_wqkT_lo[(size_t)QKD_ * H_];

// fp16 operands (linear error paths: V proj, O proj)
__device__ __half g_hs_f16[(size_t)BS_ * H_];
__device__ __half g_wvT_f16[(size_t)KD_ * H_];
__device__ __half g_at_f16[(size_t)BS_ * QD_];
__device__ __half g_woT_f16[(size_t)H_ * QD_];

// flash operands: rope'd Q (scaled) / K split-bf16, transposed V fp16
__device__ __nv_bfloat16 g_q_hi[(size_t)BS_ * QD_];
__device__ __nv_bfloat16 g_q_lo[(size_t)BS_ * QD_];
__device__ __nv_bfloat16 g_k_hi[(size_t)BS_ * KD_];
__device__ __nv_bfloat16 g_k_lo[(size_t)BS_ * KD_];
__device__ __half g_vt_f16[(size_t)B_ * NKV_ * HD_ * S_];

// ---------------------------------------------------------------------------
// PTX helpers (BASE target only)
// ---------------------------------------------------------------------------
__device__ __forceinline__ uint32_t smem_u32(const void* p) {
  uint32_t a;
  asm("{ .reg .u64 t; cvta.to.shared.u64 t, %1; cvt.u32.u64 %0, t; }"
      : "=r"(a) : "l"(p));
  return a;
}
#define SWZ128(off) ((off) ^ (((off) >> 3) & 0x70))

__device__ __forceinline__ void cp_async16(uint32_t saddr, const void* gaddr) {
  asm volatile("cp.async.cg.shared.global [%0], [%1], 16;"
               :: "r"(saddr), "l"(gaddr));
}
#define CP_COMMIT() asm volatile("cp.async.commit_group;" ::: "memory")
#define CP_WAIT(n)  asm volatile("cp.async.wait_group %0;" :: "n"(n) : "memory")

__device__ __forceinline__ void ldsm_x4(uint32_t* r, uint32_t addr) {
  asm volatile("ldmatrix.sync.aligned.m8n8.x4.shared.b16 {%0,%1,%2,%3}, [%4];"
               : "=r"(r[0]), "=r"(r[1]), "=r"(r[2]), "=r"(r[3]) : "r"(addr));
}
__device__ __forceinline__ void mma_bf16(float* d, const uint32_t* a,
                                         const uint32_t* b) {
  asm volatile(
      "mma.sync.aligned.m16n8k16.row.col.f32.bf16.bf16.f32 "
      "{%0,%1,%2,%3}, {%4,%5,%6,%7}, {%8,%9}, {%0,%1,%2,%3};"
      : "+f"(d[0]), "+f"(d[1]), "+f"(d[2]), "+f"(d[3])
      : "r"(a[0]), "r"(a[1]), "r"(a[2]), "r"(a[3]), "r"(b[0]), "r"(b[1]));
}
__device__ __forceinline__ void mma_f16(float* d, const uint32_t* a,
                                        const uint32_t* b) {
  asm volatile(
      "mma.sync.aligned.m16n8k16.row.col.f32.f16.f16.f32 "
      "{%0,%1,%2,%3}, {%4,%5,%6,%7}, {%8,%9}, {%0,%1,%2,%3};"
      : "+f"(d[0]), "+f"(d[1]), "+f"(d[2]), "+f"(d[3])
      : "r"(a[0]), "r"(a[1]), "r"(a[2]), "r"(a[3]), "r"(b[0]), "r"(b[1]));
}
__device__ __forceinline__ uint32_t pack_bf16x2(float x, float y) {
  uint32_t r;  // low half = x, high half = y
  asm("cvt.rn.bf16x2.f32 %0, %1, %2;" : "=r"(r) : "f"(y), "f"(x));
  return r;
}
__device__ __forceinline__ uint32_t pack_f16x2(float x, float y) {
  uint32_t r;  // low half = x, high half = y
  asm("cvt.rn.f16x2.f32 %0, %1, %2;" : "=r"(r) : "f"(y), "f"(x));
  return r;
}
__device__ __forceinline__ void split_pack(float x, float y,
                                           uint32_t& hi, uint32_t& lo) {
  uint32_t h = pack_bf16x2(x, y);
  float hx = __uint_as_float(h << 16);
  float hy = __uint_as_float(h & 0xFFFF0000u);
  lo = pack_bf16x2(x - hx, y - hy);
  hi = h;
}

// ---------------------------------------------------------------------------
// split conversions
// ---------------------------------------------------------------------------
// X fp32 -> bf16 hi/lo + fp16 single
__global__ void split3_kernel(const float* __restrict__ X,
                              __nv_bfloat16* __restrict__ Hi,
                              __nv_bfloat16* __restrict__ Lo,
                              __half* __restrict__ F16) {
  size_t i = ((size_t)blockIdx.x * blockDim.x + threadIdx.x) * 4;
  float4 v = *(const float4*)(X + i);
  __nv_bfloat162 h01 = __floats2bfloat162_rn(v.x, v.y);
  __nv_bfloat162 h23 = __floats2bfloat162_rn(v.z, v.w);
  float lx = v.x - __bfloat162float(h01.x);
  float ly = v.y - __bfloat162float(h01.y);
  float lz = v.z - __bfloat162float(h23.x);
  float lw = v.w - __bfloat162float(h23.y);
  *(__nv_bfloat162*)(Hi + i)     = h01;
  *(__nv_bfloat162*)(Hi + i + 2) = h23;
  *(__nv_bfloat162*)(Lo + i)     = __floats2bfloat162_rn(lx, ly);
  *(__nv_bfloat162*)(Lo + i + 2) = __floats2bfloat162_rn(lz, lw);
  *(__half2*)(F16 + i)     = __floats2half2_rn(v.x, v.y);
  *(__half2*)(F16 + i + 2) = __floats2half2_rn(v.z, v.w);
}

// W[K,N] fp32 -> T[N,K] bf16 hi/lo (transpose + split)
__global__ void transpose_split_kernel(const float* __restrict__ W,
                                       __nv_bfloat16* __restrict__ Thi,
                                       __nv_bfloat16* __restrict__ Tlo,
                                       int K, int N) {
  __shared__ float tile[32][33];
  int n0 = blockIdx.x * 32, k0 = blockIdx.y * 32;
  int tx = threadIdx.x, ty = threadIdx.y;  // 32 x 8
#pragma unroll
  for (int i = 0; i < 32; i += 8)
    tile[ty + i][tx] = W[(size_t)(k0 + ty + i) * N + n0 + tx];
  __syncthreads();
#pragma unroll
  for (int i = 0; i < 32; i += 8) {
    float v = tile[tx][ty + i];
    __nv_bfloat16 h = __float2bfloat16_rn(v);
    __nv_bfloat16 l = __float2bfloat16_rn(v - __bfloat162float(h));
    size_t o = (size_t)(n0 + ty + i) * K + k0 + tx;
    Thi[o] = h;
    Tlo[o] = l;
  }
}

// W[K,N] fp32 -> T[N,K] fp16
__global__ void transpose_f16_kernel(const float* __restrict__ W,
                                     __half* __restrict__ T,
                                     int K, int N) {
  __shared__ float tile[32][33];
  int n0 = blockIdx.x * 32, k0 = blockIdx.y * 32;
  int tx = threadIdx.x, ty = threadIdx.y;  // 32 x 8
#pragma unroll
  for (int i = 0; i < 32; i += 8)
    tile[ty + i][tx] = W[(size_t)(k0 + ty + i) * N + n0 + tx];
  __syncthreads();
#pragma unroll
  for (int i = 0; i < 32; i += 8)
    T[(size_t)(n0 + ty + i) * K + k0 + tx] = __float2half_rn(tile[tx][ty + i]);
}

// ---------------------------------------------------------------------------
// Warp-MMA split-bf16 GEMM (QK projection): C[M,N] = A[M,K] @ T[N,K]^T
// 128x128 tile/CTA, 8 warps (64x32), K chunks of 64, double-buffered.
// ---------------------------------------------------------------------------
constexpr int TILE_B    = 128 * 128;
constexpr int STAGE_B   = 4 * TILE_B;
constexpr int GEMM_SMEM = 2 * STAGE_B + 1024;

__global__ __launch_bounds__(256) void wm_gemm_kernel(
    const __nv_bfloat16* __restrict__ Ahi, const __nv_bfloat16* __restrict__ Alo,
    const __nv_bfloat16* __restrict__ Bhi, const __nv_bfloat16* __restrict__ Blo,
    float* __restrict__ C, int M, int N, int K) {
  extern __shared__ char dsm[];
  const uint32_t sbase = (smem_u32(dsm) + 1023u) & ~1023u;

  const int tid = threadIdx.x;
  const int wid = tid >> 5, lane = tid & 31;
  const int m0 = blockIdx.y * 128, n0 = blockIdx.x * 128;
  const int m0w = (wid & 1) * 64;
  const int n0w = (wid >> 1) * 32;

  const int seg = tid & 7;
  const int rb  = tid >> 3;
  const size_t Kb = (size_t)K * 2;
  const char* pAhi = (const char*)Ahi + (size_t)(m0 + rb) * Kb + seg * 16;
  const char* pAlo = (const char*)Alo + (size_t)(m0 + rb) * Kb + seg * 16;
  const char* pBhi = (const char*)Bhi + (size_t)(n0 + rb) * Kb + seg * 16;
  const char* pBlo = (const char*)Blo + (size_t)(n0 + rb) * Kb + seg * 16;

  const int rr = lane & 7;
  const int jj = lane >> 3;
  const uint32_t a_row = (uint32_t)(m0w + ((jj & 1) << 3) + rr);
  const uint32_t a_seg = (uint32_t)((jj >> 1) << 4);
  const uint32_t b_row = (uint32_t)(n0w + ((jj >> 1) << 3) + rr);
  const uint32_t b_seg = (uint32_t)((jj & 1) << 4);

  float acc[4][4][4];
#pragma unroll
  for (int i = 0; i < 4; i++)
#pragma unroll
    for (int j = 0; j < 4; j++)
#pragma unroll
      for (int t = 0; t < 4; t++) acc[i][j][t] = 0.f;

  const int NC = K / 64;

#pragma unroll
  for (int i = 0; i < 4; i++) {
    uint32_t so = SWZ128((uint32_t)((rb + 32 * i) * 128 + seg * 16));
    size_t go = (size_t)(32 * i) * Kb;
    cp_async16(sbase + so,              pAhi + go);
    cp_async16(sbase + TILE_B + so,     pAlo + go);
    cp_async16(sbase + 2 * TILE_B + so, pBhi + go);
    cp_async16(sbase + 3 * TILE_B + so, pBlo + go);
  }
  CP_COMMIT();

  for (int c = 0; c < NC; c++) {
    if (c + 1 < NC) {
      const uint32_t sb = sbase + (uint32_t)((c + 1) & 1) * STAGE_B;
      const size_t kb = (size_t)(c + 1) * 128;
#pragma unroll
      for (int i = 0; i < 4; i++) {
        uint32_t so = SWZ128((uint32_t)((rb + 32 * i) * 128 + seg * 16));
        size_t go = (size_t)(32 * i) * Kb + kb;
        cp_async16(sb + so,              pAhi + go);
        cp_async16(sb + TILE_B + so,     pAlo + go);
        cp_async16(sb + 2 * TILE_B + so, pBhi + go);
        cp_async16(sb + 3 * TILE_B + so, pBlo + go);
      }
      CP_COMMIT();
      CP_WAIT(1);
    } else {
      CP_WAIT(0);
    }
    __syncthreads();

    const uint32_t sb   = sbase + (uint32_t)(c & 1) * STAGE_B;
    const uint32_t sAhi = sb;
    const uint32_t sAlo = sb + TILE_B;
    const uint32_t sBhi = sb + 2 * TILE_B;
    const uint32_t sBlo = sb + 3 * TILE_B;

#pragma unroll
    for (int kk = 0; kk < 4; kk++) {
      uint32_t ah[4][4], al[4][4], bh[2][4], bl[2][4];
      const uint32_t kbyte = (uint32_t)(kk * 32);
#pragma unroll
      for (int mt = 0; mt < 4; mt++) {
        uint32_t off = SWZ128((a_row + mt * 16) * 128 + kbyte + a_seg);
        ldsm_x4(ah[mt], sAhi + off);
        ldsm_x4(al[mt], sAlo + off);
      }
#pragma unroll
      for (int nt = 0; nt < 2; nt++) {
        uint32_t off = SWZ128((b_row + nt * 16) * 128 + kbyte + b_seg);
        ldsm_x4(bh[nt], sBhi + off);
        ldsm_x4(bl[nt], sBlo + off);
      }
#pragma unroll
      for (int mt = 0; mt < 4; mt++)
#pragma unroll
        for (int nt8 = 0; nt8 < 4; nt8++) {
          const int n16 = nt8 >> 1, hf = (nt8 & 1) * 2;
          mma_bf16(acc[mt][nt8], ah[mt], &bh[n16][hf]);
          mma_bf16(acc[mt][nt8], ah[mt], &bl[n16][hf]);
          mma_bf16(acc[mt][nt8], al[mt], &bh[n16][hf]);
        }
    }
    __syncthreads();
  }

  const int grp = lane >> 2;
  const int cq  = (lane & 3) * 2;
#pragma unroll
  for (int mt = 0; mt < 4; mt++) {
    const int row = m0 + m0w + mt * 16 + grp;
#pragma unroll
    for (int nt8 = 0; nt8 < 4; nt8++) {
      const int col = n0 + n0w + nt8 * 8 + cq;
      float* c0 = C + (size_t)row * N + col;
      float* c1 = C + (size_t)(row + 8) * N + col;
      *(float2*)c0 = make_float2(acc[mt][nt8][0], acc[mt][nt8][1]);
      *(float2*)c1 = make_float2(acc[mt][nt8][2], acc[mt][nt8][3]);
    }
  }
}

// ---------------------------------------------------------------------------
// Warp-MMA plain-fp16 GEMM (V proj, O proj): C[M,N] = A[M,K] @ T[N,K]^T
// ---------------------------------------------------------------------------
constexpr int F16_STAGE_B = 2 * TILE_B;
constexpr int F16_SMEM    = 2 * F16_STAGE_B + 1024;

__global__ __launch_bounds__(256) void wm_gemm_f16_kernel(
    const __half* __restrict__ A, const __half* __restrict__ Bw,
    float* __restrict__ C, int M, int N, int K) {
  extern __shared__ char dsm[];
  const uint32_t sbase = (smem_u32(dsm) + 1023u) & ~1023u;

  const int tid = threadIdx.x;
  const int wid = tid >> 5, lane = tid & 31;
  const int m0 = blockIdx.y * 128, n0 = blockIdx.x * 128;
  const int m0w = (wid & 1) * 64;
  const int n0w = (wid >> 1) * 32;

  const int seg = tid & 7;
  const int rb  = tid >> 3;
  const size_t Kb = (size_t)K * 2;
  const char* pA = (const char*)A  + (size_t)(m0 + rb) * Kb + seg * 16;
  const char* pB = (const char*)Bw + (size_t)(n0 + rb) * Kb + seg * 16;

  const int rr = lane & 7;
  const int jj = lane >> 3;
  const uint32_t a_row = (uint32_t)(m0w + ((jj & 1) << 3) + rr);
  const uint32_t a_seg = (uint32_t)((jj >> 1) << 4);
  const uint32_t b_row = (uint32_t)(n0w + ((jj >> 1) << 3) + rr);
  const uint32_t b_seg = (uint32_t)((jj & 1) << 4);

  float acc[4][4][4];
#pragma unroll
  for (int i = 0; i < 4; i++)
#pragma unroll
    for (int j = 0; j < 4; j++)
#pragma unroll
      for (int t = 0; t < 4; t++) acc[i][j][t] = 0.f;

  const int NC = K / 64;

#pragma unroll
  for (int i = 0; i < 4; i++) {
    uint32_t so = SWZ128((uint32_t)((rb + 32 * i) * 128 + seg * 16));
    size_t go = (size_t)(32 * i) * Kb;
    cp_async16(sbase + so,          pA + go);
    cp_async16(sbase + TILE_B + so, pB + go);
  }
  CP_COMMIT();

  for (int c = 0; c < NC; c++) {
    if (c + 1 < NC) {
      const uint32_t sb = sbase + (uint32_t)((c + 1) & 1) * F16_STAGE_B;
      const size_t kb = (size_t)(c + 1) * 128;
#pragma unroll
      for (int i = 0; i < 4; i++) {
        uint32_t so = SWZ128((uint32_t)((rb + 32 * i) * 128 + seg * 16));
        size_t go = (size_t)(32 * i) * Kb + kb;
        cp_async16(sb + so,          pA + go);
        cp_async16(sb + TILE_B + so, pB + go);
      }
      CP_COMMIT();
      CP_WAIT(1);
    } else {
      CP_WAIT(0);
    }
    __syncthreads();

    const uint32_t sb = sbase + (uint32_t)(c & 1) * F16_STAGE_B;
    const uint32_t sA = sb;
    const uint32_t sB = sb + TILE_B;

#pragma unroll
    for (int kk = 0; kk < 4; kk++) {
      uint32_t af[4][4], bf[2][4];
      const uint32_t kbyte = (uint32_t)(kk * 32);
#pragma unroll
      for (int mt = 0; mt < 4; mt++) {
        uint32_t off = SWZ128((a_row + mt * 16) * 128 + kbyte + a_seg);
        ldsm_x4(af[mt], sA + off);
      }
#pragma unroll
      for (int nt = 0; nt < 2; nt++) {
        uint32_t off = SWZ128((b_row + nt * 16) * 128 + kbyte + b_seg);
        ldsm_x4(bf[nt], sB + off);
      }
#pragma unroll
      for (int mt = 0; mt < 4; mt++)
#pragma unroll
        for (int nt8 = 0; nt8 < 4; nt8++) {
          const int n16 = nt8 >> 1, hf = (nt8 & 1) * 2;
          mma_f16(acc[mt][nt8], af[mt], &bf[n16][hf]);
        }
    }
    __syncthreads();
  }

  const int grp = lane >> 2;
  const int cq  = (lane & 3) * 2;
#pragma unroll
  for (int mt = 0; mt < 4; mt++) {
    const int row = m0 + m0w + mt * 16 + grp;
#pragma unroll
    for (int nt8 = 0; nt8 < 4; nt8++) {
      const int col = n0 + n0w + nt8 * 8 + cq;
      float* c0 = C + (size_t)row * N + col;
      float* c1 = C + (size_t)(row + 8) * N + col;
      *(float2*)c0 = make_float2(acc[mt][nt8][0], acc[mt][nt8][1]);
      *(float2*)c1 = make_float2(acc[mt][nt8][2], acc[mt][nt8][3]);
    }
  }
}

// ---------------------------------------------------------------------------
// RoPE + split to bf16 hi/lo from fused qk buffer. Q gets softmax scale.
// ---------------------------------------------------------------------------
__global__ void rope_split_kernel(const float* __restrict__ qk,
                                  const float* __restrict__ cosb,
                                  const float* __restrict__ sinb,
                                  __nv_bfloat16* __restrict__ qhi,
                                  __nv_bfloat16* __restrict__ qlo,
                                  __nv_bfloat16* __restrict__ khi,
                                  __nv_bfloat16* __restrict__ klo) {
  int gid = blockIdx.x * blockDim.x + threadIdx.x;
  int d = gid & 63;
  int t = gid >> 6;
  int hh = t % (NH_ + NKV_);
  int bs = t / (NH_ + NKV_);
  float c  = cosb[bs * HD_ + d];
  float sn = sinb[bs * HD_ + d];
  if (hh < NH_) {
    size_t src = (size_t)bs * QKD_ + hh * HD_ + d;
    size_t off = (size_t)bs * QD_ + hh * HD_ + d;
    const float scale = 0.08838834764831845f;  // 1/sqrt(128)
    float x1 = qk[src], x2 = qk[src + 64];
    float y1 = (x1 * c - x2 * sn) * scale;
    float y2 = (x2 * c + x1 * sn) * scale;
    __nv_bfloat16 h1 = __float2bfloat16_rn(y1);
    __nv_bfloat16 h2 = __float2bfloat16_rn(y2);
    qhi[off]      = h1;
    qlo[off]      = __float2bfloat16_rn(y1 - __bfloat162float(h1));
    qhi[off + 64] = h2;
    qlo[off + 64] = __float2bfloat16_rn(y2 - __bfloat162float(h2));
  } else {
    int kvh = hh - NH_;
    size_t src = (size_t)bs * QKD_ + QD_ + kvh * HD_ + d;
    size_t off = (size_t)bs * KD_ + kvh * HD_ + d;
    float x1 = qk[src], x2 = qk[src + 64];
    float y1 = x1 * c - x2 * sn;
    float y2 = x2 * c + x1 * sn;
    __nv_bfloat16 h1 = __float2bfloat16_rn(y1);
    __nv_bfloat16 h2 = __float2bfloat16_rn(y2);
    khi[off]      = h1;
    klo[off]      = __float2bfloat16_rn(y1 - __bfloat162float(h1));
    khi[off + 64] = h2;
    klo[off + 64] = __float2bfloat16_rn(y2 - __bfloat162float(h2));
  }
}

// V [b*S+s][kvh*128+d] fp32 -> Vt [(b*NKV+kvh)*128+d][s] fp16
__global__ void vt_f16_kernel(const float* __restrict__ v,
                              __half* __restrict__ vt) {
  __shared__ float tl[32][33];
  int s0 = blockIdx.x * 32, d0 = blockIdx.y * 32, bh = blockIdx.z;
  int b = bh >> 3, kvh = bh & 7;
  int tx = threadIdx.x, ty = threadIdx.y;  // 32 x 8
#pragma unroll
  for (int i = 0; i < 32; i += 8)
    tl[ty + i][tx] = v[(size_t)(b * S_ + s0 + ty + i) * KD_ + kvh * HD_ + d0 + tx];
  __syncthreads();
#pragma unroll
  for (int i = 0; i < 32; i += 8) {
    size_t o = ((size_t)bh * HD_ + d0 + ty + i) * S_ + s0 + tx;
    vt[o] = __float2half_rn(tl[tx][ty + i]);
  }
}

// ---------------------------------------------------------------------------
// Flash attention: QK split-bf16 (3 products), PV plain fp16 (1 product).
// BQ=128 (8 warps x m16), BKT=64, double-buffered K/V, Q resident.
// smem: Q 64K | K bufs 2x32K | V bufs 2x16K = 160 KB
// ---------------------------------------------------------------------------
constexpr int FLASH2_SMEM = 163840;

__global__ __launch_bounds__(256, 1) void flash_hmma_kernel(
    const __nv_bfloat16* __restrict__ Qhi_g, const __nv_bfloat16* __restrict__ Qlo_g,
    const __nv_bfloat16* __restrict__ Khi_g, const __nv_bfloat16* __restrict__ Klo_g,
    const __half* __restrict__ Vt_g,
    __half* __restrict__ Of16_g) {
  extern __shared__ char sm[];
  const uint32_t sb = smem_u32(sm);
  const int qt = blockIdx.x, h = blockIdx.y, b = blockIdx.z;
  const int kvh = h >> 2;                 // n_rep = 4
  const int tid = threadIdx.x, wid = tid >> 5, lane = tid & 31;
  const int q0 = qt * 128;
  const int q0w = q0 + wid * 16;

  const uint32_t sQhi = sb;               // 2 chunks of 16KB (d halves)
  const uint32_t sQlo = sb + 32768;
  const uint32_t sKb  = sb + 65536;       // + buf*32768; hi chunks 0/8K, lo +16K
  const uint32_t sVb  = sb + 131072;      // + buf*16384 (fp16 single)

  // ---- Q tile load (hi+lo) ----
  {
    const int seg = tid & 15, r0 = tid >> 4;
    const size_t qoff = ((size_t)(b * S_ + q0) * QD_ + h * HD_) * 2;
    const char* ph = (const char*)Qhi_g + qoff;
    const char* pl = (const char*)Qlo_g + qoff;
#pragma unroll
    for (int i = 0; i < 8; i++) {
      int r = r0 + i * 16;
      uint32_t off = ((seg >> 3) * 16384) +
                     SWZ128((uint32_t)(r * 128 + (seg & 7) * 16));
      size_t g = (size_t)r * (QD_ * 2) + seg * 16;
      cp_async16(sQhi + off, ph + g);
      cp_async16(sQlo + off, pl + g);
    }
  }
  CP_COMMIT();

  const int nkt = 2 * qt + 2;

  auto load_kv = [&](int kt, int buf) {
    const uint32_t sK = sKb + (uint32_t)buf * 32768;
    const uint32_t sV = sVb + (uint32_t)buf * 16384;
    {
      const int seg = tid & 15, r0 = tid >> 4;
      const size_t koff = ((size_t)(b * S_ + kt * 64) * KD_ + kvh * HD_) * 2;
      const char* ph = (const char*)Khi_g + koff;
      const char* pl = (const char*)Klo_g + koff;
#pragma unroll
      for (int i = 0; i < 4; i++) {
        int r = r0 + i * 16;
        uint32_t off = ((seg >> 3) * 8192) +
                       SWZ128((uint32_t)(r * 128 + (seg & 7) * 16));
        size_t g = (size_t)r * (KD_ * 2) + seg * 16;
        cp_async16(sK + off,         ph + g);
        cp_async16(sK + 16384 + off, pl + g);
      }
    }
    {
      const int seg = tid & 7, d0 = tid >> 3;
      const size_t voff = ((size_t)(b * NKV_ + kvh) * HD_ * S_ + (size_t)kt * 64) * 2;
      const char* pv = (const char*)Vt_g + voff;
#pragma unroll
      for (int i = 0; i < 4; i++) {
        int d = d0 + i * 32;
        uint32_t off = SWZ128((uint32_t)(d * 128 + seg * 16));
        size_t g = (size_t)d * (S_ * 2) + seg * 16;
        cp_async16(sV + off, pv + g);
      }
    }
    CP_COMMIT();
  };

  load_kv(0, 0);

  // fragment addressing
  const int rr = lane & 7, jj = lane >> 3;
  const uint32_t a_row = (uint32_t)(wid * 16 + ((jj & 1) << 3) + rr);
  const uint32_t a_seg = (uint32_t)((jj >> 1) << 4);
  const uint32_t b_rw  = (uint32_t)(((jj >> 1) << 3) + rr);
  const uint32_t b_seg = (uint32_t)((jj & 1) << 4);

  float oa[16][4];
#pragma unroll
  for (int g = 0; g < 16; g++)
#pragma unroll
    for (int t = 0; t < 4; t++) oa[g][t] = 0.f;
  float m0 = -INFINITY, m1 = -INFINITY, l0 = 0.f, l1 = 0.f;

  for (int kt = 0; kt < nkt; kt++) {
    const int buf = kt & 1;
    if (kt + 1 < nkt) {
      load_kv(kt + 1, buf ^ 1);
      CP_WAIT(1);
    } else {
      CP_WAIT(0);
    }
    __syncthreads();

    if (kt * 64 <= q0w + 15) {  // tile intersects this warp's rows
      const uint32_t sK = sKb + (uint32_t)buf * 32768;
      const uint32_t sV = sVb + (uint32_t)buf * 16384;

      // ---- S = Q @ K^T (split-bf16, 3 products) ----
      float sa[8][4];
#pragma unroll
      for (int t = 0; t < 8; t++)
#pragma unroll
        for (int e = 0; e < 4; e++) sa[t][e] = 0.f;

#pragma unroll
      for (int kk = 0; kk < 8; kk++) {
        uint32_t ah[4], al[4];
        uint32_t qo = ((uint32_t)(kk >> 2) * 16384) +
                      SWZ128(a_row * 128 + (uint32_t)(kk & 3) * 32 + a_seg);
        ldsm_x4(ah, sQhi + qo);
        ldsm_x4(al, sQlo + qo);
#pragma unroll
        for (int nt = 0; nt < 4; nt++) {
          uint32_t bhf[4], blf[4];
          uint32_t ko = ((uint32_t)(kk >> 2) * 8192) +
                        SWZ128((b_rw + nt * 16) * 128 + (uint32_t)(kk & 3) * 32 + b_seg);
          ldsm_x4(bhf, sK + ko);
          ldsm_x4(blf, sK + 16384 + ko);
          mma_bf16(sa[nt * 2],     ah, &bhf[0]);
          mma_bf16(sa[nt * 2],     ah, &blf[0]);
          mma_bf16(sa[nt * 2],     al, &bhf[0]);
          mma_bf16(sa[nt * 2 + 1], ah, &bhf[2]);
          mma_bf16(sa[nt * 2 + 1], ah, &blf[2]);
          mma_bf16(sa[nt * 2 + 1], al, &bhf[2]);
        }
      }

      // ---- causal mask ----
      if (kt * 64 + 63 > q0w) {
        int r0g = q0w + (lane >> 2);
#pragma unroll
        for (int t = 0; t < 8; t++) {
          int c0 = kt * 64 + t * 8 + ((lane & 3) << 1);
          if (c0     > r0g)     sa[t][0] = -1e30f;
          if (c0 + 1 > r0g)     sa[t][1] = -1e30f;
          if (c0     > r0g + 8) sa[t][2] = -1e30f;
          if (c0 + 1 > r0g + 8) sa[t][3] = -1e30f;
        }
      }

      // ---- online softmax (rows r, r+8) ----
      float mx0 = -INFINITY, mx1 = -INFINITY;
#pragma unroll
      for (int t = 0; t < 8; t++) {
        mx0 = fmaxf(mx0, fmaxf(sa[t][0], sa[t][1]));
        mx1 = fmaxf(mx1, fmaxf(sa[t][2], sa[t][3]));
      }
      mx0 = fmaxf(mx0, __shfl_xor_sync(0xffffffffu, mx0, 1));
      mx0 = fmaxf(mx0, __shfl_xor_sync(0xffffffffu, mx0, 2));
      mx1 = fmaxf(mx1, __shfl_xor_sync(0xffffffffu, mx1, 1));
      mx1 = fmaxf(mx1, __shfl_xor_sync(0xffffffffu, mx1, 2));
      float mn0 = fmaxf(m0, mx0), mn1 = fmaxf(m1, mx1);
      float f0 = __expf(m0 - mn0), f1 = __expf(m1 - mn1);
      m0 = mn0; m1 = mn1;
      float s0 = 0.f, s1 = 0.f;
#pragma unroll
      for (int t = 0; t < 8; t++) {
        sa[t][0] = __expf(sa[t][0] - mn0);
        sa[t][1] = __expf(sa[t][1] - mn0);
        sa[t][2] = __expf(sa[t][2] - mn1);
        sa[t][3] = __expf(sa[t][3] - mn1);
        s0 += sa[t][0] + sa[t][1];
        s1 += sa[t][2] + sa[t][3];
      }
      s0 += __shfl_xor_sync(0xffffffffu, s0, 1);
      s0 += __shfl_xor_sync(0xffffffffu, s0, 2);
      s1 += __shfl_xor_sync(0xffffffffu, s1, 1);
      s1 += __shfl_xor_sync(0xffffffffu, s1, 2);
      l0 = l0 * f0 + s0;
      l1 = l1 * f1 + s1;
#pragma unroll
      for (int g = 0; g < 16; g++) {
        oa[g][0] *= f0; oa[g][1] *= f0;
        oa[g][2] *= f1; oa[g][3] *= f1;
      }

      // ---- O += P @ V  (P fp16, V fp16, 1 product) ----
#pragma unroll
      for (int kk2 = 0; kk2 < 4; kk2++) {
        uint32_t ap[4];
        ap[0] = pack_f16x2(sa[2 * kk2][0],     sa[2 * kk2][1]);
        ap[1] = pack_f16x2(sa[2 * kk2][2],     sa[2 * kk2][3]);
        ap[2] = pack_f16x2(sa[2 * kk2 + 1][0], sa[2 * kk2 + 1][1]);
        ap[3] = pack_f16x2(sa[2 * kk2 + 1][2], sa[2 * kk2 + 1][3]);
#pragma unroll
        for (int g7 = 0; g7 < 8; g7++) {
          uint32_t bv[4];
          uint32_t vo = SWZ128((g7 * 16 + b_rw) * 128 + (uint32_t)kk2 * 32 + b_seg);
          ldsm_x4(bv, sV + vo);
          mma_f16(oa[g7 * 2],     ap, &bv[0]);
          mma_f16(oa[g7 * 2 + 1], ap, &bv[2]);
        }
      }
    }
    __syncthreads();
  }

  // ---- epilogue: normalize and store fp16 directly ----
  {
    float inv0 = 1.f / l0, inv1 = 1.f / l1;
    const size_t r0 = (size_t)(b * S_ + q0w + (lane >> 2)) * QD_;
    const size_t r1 = r0 + (size_t)8 * QD_;
    const int cb = h * HD_ + ((lane & 3) << 1);
#pragma unroll
    for (int g = 0; g < 16; g++) {
      __half2 p0 = __floats2half2_rn(oa[g][0] * inv0, oa[g][1] * inv0);
      __half2 p1 = __floats2half2_rn(oa[g][2] * inv1, oa[g][3] * inv1);
      *(__half2*)(Of16_g + r0 + cb + g * 8) = p0;
      *(__half2*)(Of16_g + r1 + cb + g * 8) = p1;
    }
  }
}

// ---------------------------------------------------------------------------
extern "C" void kernel_launch(void* const* d_in, const int* in_sizes, int n_in,
                              void* d_out, int out_size) {
  const float* hs   = (const float*)d_in[0];
  const float* cosb = (const float*)d_in[1];
  const float* sinb = (const float*)d_in[2];
  const float* wq   = (const float*)d_in[3];
  const float* wk   = (const float*)d_in[4];
  const float* wv   = (const float*)d_in[5];
  const float* wo   = (const float*)d_in[6];
  float* out = (float*)d_out;

  float *qk, *vbuf;
  cudaGetSymbolAddress((void**)&qk, g_qk);
  cudaGetSymbolAddress((void**)&vbuf, g_v);

  __nv_bfloat16 *hshi, *hslo, *wqkh, *wqkl;
  __nv_bfloat16 *qhi, *qlo, *khi, *klo;
  __half *hsf, *wvf, *atf, *wof, *vtf;
  cudaGetSymbolAddress((void**)&hshi, g_hs_hi);
  cudaGetSymbolAddress((void**)&hslo, g_hs_lo);
  cudaGetSymbolAddress((void**)&wqkh, g_wqkT_hi);
  cudaGetSymbolAddress((void**)&wqkl, g_wqkT_lo);
  cudaGetSymbolAddress((void**)&hsf, g_hs_f16);
  cudaGetSymbolAddress((void**)&wvf, g_wvT_f16);
  cudaGetSymbolAddress((void**)&atf, g_at_f16);
  cudaGetSymbolAddress((void**)&wof, g_woT_f16);
  cudaGetSymbolAddress((void**)&qhi, g_q_hi);
  cudaGetSymbolAddress((void**)&qlo, g_q_lo);
  cudaGetSymbolAddress((void**)&khi, g_k_hi);
  cudaGetSymbolAddress((void**)&klo, g_k_lo);
  cudaGetSymbolAddress((void**)&vtf, g_vt_f16);

  cudaFuncSetAttribute(wm_gemm_kernel,
                       cudaFuncAttributeMaxDynamicSharedMemorySize, GEMM_SMEM);
  cudaFuncSetAttribute(wm_gemm_f16_kernel,
                       cudaFuncAttributeMaxDynamicSharedMemorySize, F16_SMEM);
  cudaFuncSetAttribute(flash_hmma_kernel,
                       cudaFuncAttributeMaxDynamicSharedMemorySize, FLASH2_SMEM);

  // preprocess: hidden states (hi/lo/f16); weights transposed
  split3_kernel<<<(size_t)BS_ * H_ / 1024, 256>>>(hs, hshi, hslo, hsf);
  transpose_split_kernel<<<dim3(QD_ / 32, H_ / 32), dim3(32, 8)>>>(
      wq, wqkh, wqkl, H_, QD_);
  transpose_split_kernel<<<dim3(KD_ / 32, H_ / 32), dim3(32, 8)>>>(
      wk, wqkh + (size_t)QD_ * H_, wqkl + (size_t)QD_ * H_, H_, KD_);
  transpose_f16_kernel<<<dim3(KD_ / 32, H_ / 32), dim3(32, 8)>>>(
      wv, wvf, H_, KD_);
  transpose_f16_kernel<<<dim3(H_ / 32, QD_ / 32), dim3(32, 8)>>>(
      wo, wof, QD_, H_);

  // projections: Q|K split-bf16 (3 products), V plain fp16 (1 product)
  wm_gemm_kernel<<<dim3(QKD_ / 128, BS_ / 128), 256, GEMM_SMEM>>>(
      hshi, hslo, wqkh, wqkl, qk, BS_, QKD_, H_);
  wm_gemm_f16_kernel<<<dim3(KD_ / 128, BS_ / 128), 256, F16_SMEM>>>(
      hsf, wvf, vbuf, BS_, KD_, H_);

  // RoPE + split (scale folded into Q); V transpose to fp16
  {
    int total = B_ * S_ * (NH_ + NKV_) * 64;
    rope_split_kernel<<<total / 256, 256>>>(qk, cosb, sinb, qhi, qlo, khi, klo);
  }
  vt_f16_kernel<<<dim3(S_ / 32, HD_ / 32, B_ * NKV_), dim3(32, 8)>>>(vbuf, vtf);

  // Causal GQA flash attention (QK split-bf16, PV fp16)
  flash_hmma_kernel<<<dim3(S_ / 128, NH_, B_), 256, FLASH2_SMEM>>>(
      qhi, qlo, khi, klo, vtf, atf);

  // O projection (plain fp16, 1 product)
  wm_gemm_f16_kernel<<<dim3(H_ / 128, BS_ / 128), 256, F16_SMEM>>>(
      atf, wof, out, BS_, H_, QD_);
}